// round 1
// baseline (speedup 1.0000x reference)
#include <cuda_runtime.h>
#include <cuda_bf16.h>
#include <cstdint>

// Problem constants
#define BB   4
#define LL   2048
#define DM   1024
#define KH   32        // heads
#define HD   32        // head dim
#define MT   4         // m_theta
#define TOT  2080      // 2*DM + KH
#define CONVK 4
#define ANCHOR 4
#define TT   8         // scan tile (time steps per tile)

// Scratch (static device globals — no runtime allocation allowed)
__device__ float g_z [BB * LL * TOT];   // x @ W_in
__device__ float g_zc[BB * LL * TOT];   // after causal depthwise conv
__device__ float g_g [BB * LL * DM];    // gated y (input to final GEMM)

// ---------------------------------------------------------------------------
// SGEMM: C(M,N) = A(M,K) * B(K,N), all row-major fp32.
// Requirements: M % 128 == 0, K % 16 == 0, N % 4 == 0 (N bound-checked).
// 128x128 block tile, 16 K-slice, 8x8 per-thread micro tile, 256 threads.
// ---------------------------------------------------------------------------
__global__ __launch_bounds__(256) void sgemm128(
    const float* __restrict__ A, const float* __restrict__ Bm,
    float* __restrict__ C, int M, int N, int Kd)
{
    __shared__ float As[16][128];
    __shared__ float Bs[16][128];

    const int tid = threadIdx.x;
    const int row0 = blockIdx.y * 128;
    const int col0 = blockIdx.x * 128;

    const int arow = tid >> 2;          // 0..63
    const int acol = (tid & 3) * 4;     // 0,4,8,12
    const int brow = tid >> 5;          // 0..7
    const int bcol = (tid & 31) * 4;    // 0..124

    const int tx = tid & 15;
    const int ty = tid >> 4;

    float acc[8][8];
#pragma unroll
    for (int i = 0; i < 8; ++i)
#pragma unroll
        for (int jcol = 0; jcol < 8; ++jcol) acc[i][jcol] = 0.0f;

    const int gcol = col0 + bcol;
    const bool bvalid = (gcol < N);

    for (int k0 = 0; k0 < Kd; k0 += 16) {
        // Load A tile (transposed into As[k][m])
        float4 a0 = *(const float4*)(A + (size_t)(row0 + arow) * Kd + k0 + acol);
        float4 a1 = *(const float4*)(A + (size_t)(row0 + arow + 64) * Kd + k0 + acol);
        As[acol + 0][arow] = a0.x; As[acol + 1][arow] = a0.y;
        As[acol + 2][arow] = a0.z; As[acol + 3][arow] = a0.w;
        As[acol + 0][arow + 64] = a1.x; As[acol + 1][arow + 64] = a1.y;
        As[acol + 2][arow + 64] = a1.z; As[acol + 3][arow + 64] = a1.w;

        // Load B tile
        float4 b0 = make_float4(0.f, 0.f, 0.f, 0.f), b1 = b0;
        if (bvalid) {
            b0 = *(const float4*)(Bm + (size_t)(k0 + brow) * N + gcol);
            b1 = *(const float4*)(Bm + (size_t)(k0 + brow + 8) * N + gcol);
        }
        *(float4*)&Bs[brow][bcol]     = b0;
        *(float4*)&Bs[brow + 8][bcol] = b1;
        __syncthreads();

#pragma unroll
        for (int kk = 0; kk < 16; ++kk) {
            float4 ar0 = *(const float4*)&As[kk][ty * 8];
            float4 ar1 = *(const float4*)&As[kk][ty * 8 + 4];
            float4 br0 = *(const float4*)&Bs[kk][tx * 8];
            float4 br1 = *(const float4*)&Bs[kk][tx * 8 + 4];
            float ar[8] = {ar0.x, ar0.y, ar0.z, ar0.w, ar1.x, ar1.y, ar1.z, ar1.w};
            float br[8] = {br0.x, br0.y, br0.z, br0.w, br1.x, br1.y, br1.z, br1.w};
#pragma unroll
            for (int i = 0; i < 8; ++i)
#pragma unroll
                for (int jcol = 0; jcol < 8; ++jcol)
                    acc[i][jcol] += ar[i] * br[jcol];
        }
        __syncthreads();
    }

#pragma unroll
    for (int i = 0; i < 8; ++i) {
        int row = row0 + ty * 8 + i;
#pragma unroll
        for (int q = 0; q < 2; ++q) {
            int col = col0 + tx * 8 + q * 4;
            if (col < N) {
                *(float4*)(C + (size_t)row * N + col) =
                    make_float4(acc[i][q * 4], acc[i][q * 4 + 1],
                                acc[i][q * 4 + 2], acc[i][q * 4 + 3]);
            }
        }
    }
}

// ---------------------------------------------------------------------------
// Causal depthwise conv1d, kernel 4, left pad 3:
//   zc[b,l,c] = sum_j z[b, l-3+j, c] * w_conv[j, 0, c] + b_conv[c]
// ---------------------------------------------------------------------------
__global__ __launch_bounds__(256) void conv_kernel(
    const float* __restrict__ z, const float* __restrict__ wc,
    const float* __restrict__ bc, float* __restrict__ zc)
{
    int idx = blockIdx.x * 256 + threadIdx.x;
    const int total = BB * LL * TOT;
    if (idx >= total) return;
    int c  = idx % TOT;
    int bl = idx / TOT;
    int l  = bl % LL;

    float acc = bc[c];
#pragma unroll
    for (int jk = 0; jk < CONVK; ++jk) {
        int ls = l - 3 + jk;
        if (ls >= 0)
            acc += wc[jk * TOT + c] * z[(size_t)(bl - 3 + jk) * TOT + c];
    }
    zc[idx] = acc;
}

// ---------------------------------------------------------------------------
// Fused scan kernel: one block per (batch, head). 128 threads = (h, m) lanes.
// Per time step: conv outputs -> p, time weight, phase features, 3 causal
// accumulators; then ratio, joint RMS norm, 128->32 head projection, SiLU gate.
// Writes g[b,l,d] = y * gate.
// ---------------------------------------------------------------------------
__global__ __launch_bounds__(128) void scan_kernel(
    const float* __restrict__ zc, const float* __restrict__ theta,
    const float* __restrict__ dslopes, const float* __restrict__ aslopes,
    const float* __restrict__ sscale, const float* __restrict__ dlogits,
    const float* __restrict__ nscale, const float* __restrict__ W_re,
    const float* __restrict__ W_im, float* __restrict__ g_out)
{
    extern __shared__ float sm[];
    float* Wre_s = sm;                 // 4096
    float* Wim_s = sm + 4096;          // 4096
    float* sre   = sm + 8192;          // 128*12 (stride 12 -> 16B-aligned float4, low conflict)
    float* sim   = sm + 9728;          // 128*12
    float* ssq   = sm + 11264;         // 8*128
    float* sxv   = sm + 12288;         // 8*32
    float* sgv   = sm + 12544;         // 8*32
    float* ssv   = sm + 12800;         // 8
    float* srsq  = sm + 12808;         // 8
    float* ypart = sm + 12816;         // 4*8*32
    // total 13840 floats = 55360 B

    const int blk = blockIdx.x;
    const int bb  = blk >> 5;          // batch
    const int k   = blk & 31;          // head
    const int tid = threadIdx.x;
    const int j   = tid;               // (h,m) flat index, j = h*4 + m
    const int h   = j >> 2;
    const int lane = tid & 31;
    const int warp = tid >> 5;
    const int c  = warp;               // j-chunk for projection
    const int hp = lane;               // output dim for projection

    // Per-thread constants
    const float theta_t = theta[k * (HD * MT) + j];
    const float ns_re = nscale[j];
    const float ns_im = nscale[HD * MT + j];

    float dl0 = dlogits[0], dl1 = dlogits[1], dl2 = dlogits[2];
    float mx = fmaxf(dl0, fmaxf(dl1, dl2));
    float e0 = __expf(dl0 - mx), e1 = __expf(dl1 - mx), e2 = __expf(dl2 - mx);
    float dinv = 1.0f / (e0 + e1 + e2);
    const float w0 = e0 * dinv, w1 = e1 * dinv, w2 = e2 * dinv;

    const float ss = sscale[k];
    const bool decay = (k < KH - ANCHOR);
    const float slope = decay ? dslopes[k] : aslopes[k - (KH - ANCHOR)];
    const float rate = logf(1.0f + expf(slope));   // softplus

    // Load projection weights into shared
    for (int i = tid; i < HD * MT * HD; i += 128) {
        Wre_s[i] = W_re[i];
        Wim_s[i] = W_im[i];
    }

    float accRe = 0.0f, accIm = 0.0f, accDen = 0.0f;
    const size_t baserow = (size_t)bb * LL;

    for (int l0 = 0; l0 < LL; l0 += TT) {
        __syncthreads();   // protect shared reuse across tiles
        // --- phase 1: cooperative load of this tile's conv outputs ---
        {
            int v = tid;
            int t = v >> 5, hh = v & 31;
            size_t rowA = (baserow + l0 + t) * (size_t)TOT;
            sxv[v] = zc[rowA + (size_t)k * HD + hh];
            sgv[v] = zc[rowA + DM + (size_t)k * HD + hh];
            v = tid + 128;
            t = v >> 5; hh = v & 31;
            size_t rowB = (baserow + l0 + t) * (size_t)TOT;
            sxv[v] = zc[rowB + (size_t)k * HD + hh];
            sgv[v] = zc[rowB + DM + (size_t)k * HD + hh];
            if (tid < TT)
                ssv[tid] = zc[(baserow + l0 + tid) * (size_t)TOT + 2 * DM + k];
        }
        __syncthreads();

        // --- phase 2: sequential scan over T steps (per-thread accumulators) ---
#pragma unroll
        for (int t = 0; t < TT; ++t) {
            int l = l0 + t;
            float xv = sxv[t * 32 + h];
            float sv = ssv[t];
            float parg = fminf(fmaxf(ss * sv, -20.0f), 20.0f);
            float p = __expf(parg);
            float tw = decay ? __expf(-rate * (float)(LL - 1 - l))
                             : __expf(-rate * (float)l);
            float pw = p * tw;
            float phi = xv * theta_t;
            float sb, cb;
            __sincosf(phi, &sb, &cb);
            float poly = w0 + w1 * xv - w2 * xv * xv;
            float ppw = pw * poly;
            accDen += pw;
            accRe  += ppw * cb;
            accIm  += ppw * sb;
            float invd = 1.0f / fmaxf(accDen, 1e-4f);
            float re = accRe * invd;
            float im = accIm * invd;
            sre[j * 12 + t] = re;
            sim[j * 12 + t] = im;
            ssq[t * 128 + j] = re * re + im * im;
        }
        __syncthreads();

        // --- phase 3: joint RMS statistic per step (each warp handles 2 steps) ---
        {
            int tt = warp * 2;
#pragma unroll
            for (int q = 0; q < 2; ++q, ++tt) {
                float v = ssq[tt * 128 + lane] + ssq[tt * 128 + lane + 32]
                        + ssq[tt * 128 + lane + 64] + ssq[tt * 128 + lane + 96];
#pragma unroll
                for (int off = 16; off; off >>= 1)
                    v += __shfl_xor_sync(0xffffffffu, v, off);
                if (lane == 0)
                    srsq[tt] = rsqrtf(v * (1.0f / (2.0f * HD * MT)) + 1e-5f);
            }
        }
        __syncthreads();

        // --- phase 4: normalize in place ---
#pragma unroll
        for (int t = 0; t < TT; ++t) {
            float r = srsq[t];
            sre[j * 12 + t] *= r * ns_re;
            sim[j * 12 + t] *= r * ns_im;
        }
        __syncthreads();

        // --- phase 5: head projection y = re_n @ W_re + im_n @ W_im ---
        float acc[TT];
#pragma unroll
        for (int t = 0; t < TT; ++t) acc[t] = 0.0f;
#pragma unroll 8
        for (int jj = 0; jj < 32; ++jj) {
            int jg = c * 32 + jj;
            float wr = Wre_s[jg * 32 + hp];
            float wi = Wim_s[jg * 32 + hp];
            float4 r0 = *(const float4*)(sre + jg * 12);
            float4 r1 = *(const float4*)(sre + jg * 12 + 4);
            float4 i0 = *(const float4*)(sim + jg * 12);
            float4 i1 = *(const float4*)(sim + jg * 12 + 4);
            acc[0] += r0.x * wr + i0.x * wi;
            acc[1] += r0.y * wr + i0.y * wi;
            acc[2] += r0.z * wr + i0.z * wi;
            acc[3] += r0.w * wr + i0.w * wi;
            acc[4] += r1.x * wr + i1.x * wi;
            acc[5] += r1.y * wr + i1.y * wi;
            acc[6] += r1.z * wr + i1.z * wi;
            acc[7] += r1.w * wr + i1.w * wi;
        }
#pragma unroll
        for (int t = 0; t < TT; ++t)
            ypart[(c * TT + t) * 32 + hp] = acc[t];
        __syncthreads();

        // --- phase 6: reduce partials, SiLU gate, store ---
        for (int v = tid; v < TT * 32; v += 128) {
            int t = v >> 5, hh = v & 31;
            float y = ypart[t * 32 + hh] + ypart[(TT + t) * 32 + hh]
                    + ypart[(2 * TT + t) * 32 + hh] + ypart[(3 * TT + t) * 32 + hh];
            float gz = sgv[t * 32 + hh];
            float gate = gz / (1.0f + __expf(-gz));
            g_out[(baserow + l0 + t) * (size_t)DM + (size_t)k * HD + hh] = y * gate;
        }
    }
}

// ---------------------------------------------------------------------------
extern "C" void kernel_launch(void* const* d_in, const int* in_sizes, int n_in,
                              void* d_out, int out_size)
{
    const float* x       = (const float*)d_in[0];
    const float* W_in    = (const float*)d_in[1];
    const float* w_conv  = (const float*)d_in[2];
    const float* b_conv  = (const float*)d_in[3];
    const float* theta   = (const float*)d_in[4];
    const float* dslopes = (const float*)d_in[5];
    const float* aslopes = (const float*)d_in[6];
    const float* sscale  = (const float*)d_in[7];
    const float* dlogits = (const float*)d_in[8];
    const float* nscale  = (const float*)d_in[9];
    const float* W_re    = (const float*)d_in[10];
    const float* W_im    = (const float*)d_in[11];
    const float* W_out   = (const float*)d_in[12];
    float* out = (float*)d_out;

    float *pz, *pzc, *pg;
    cudaGetSymbolAddress((void**)&pz,  g_z);
    cudaGetSymbolAddress((void**)&pzc, g_zc);
    cudaGetSymbolAddress((void**)&pg,  g_g);

    // 1) z = x @ W_in   (8192 x 2080, K=1024)
    {
        dim3 grid((TOT + 127) / 128, (BB * LL) / 128);
        sgemm128<<<grid, 256>>>(x, W_in, pz, BB * LL, TOT, DM);
    }
    // 2) causal depthwise conv
    {
        int total = BB * LL * TOT;
        conv_kernel<<<(total + 255) / 256, 256>>>(pz, w_conv, b_conv, pzc);
    }
    // 3) fused scan + norm + head projection + gate
    {
        cudaFuncSetAttribute(scan_kernel,
                             cudaFuncAttributeMaxDynamicSharedMemorySize,
                             56 * 1024);
        scan_kernel<<<BB * KH, 128, 55360>>>(pzc, theta, dslopes, aslopes,
                                             sscale, dlogits, nscale,
                                             W_re, W_im, pg);
    }
    // 4) out = g @ W_out  (8192 x 1024, K=1024)
    {
        dim3 grid(DM / 128, (BB * LL) / 128);
        sgemm128<<<grid, 256>>>(pg, W_out, out, BB * LL, DM, DM);
    }
}

// round 3
// speedup vs baseline: 1.6473x; 1.6473x over previous
#include <cuda_runtime.h>
#include <cuda_bf16.h>
#include <cstdint>

// Problem constants
#define BB   4
#define LL   2048
#define DM   1024
#define KH   32        // heads
#define HD   32        // head dim
#define MT   4         // m_theta
#define TOT  2080      // 2*DM + KH
#define CONVK 4
#define ANCHOR 4
#define TT   8         // scan tile (time steps per tile)

// Scratch (static device globals — no runtime allocation allowed)
__device__ float g_z  [BB * LL * TOT];   // x @ W_in
__device__ float g_zc [BB * LL * TOT];   // after causal depthwise conv
__device__ float g_g  [BB * LL * DM];    // gated y (input to final GEMM)
__device__ float g_bt1[TOT * DM];        // W_in^T  (2080 x 1024), K-major rows
__device__ float g_bt2[DM * DM];         // W_out^T (1024 x 1024)

// ---------------------------------------------------------------------------
// Tiled transpose: D[C][R] = S[R][C]^T
// ---------------------------------------------------------------------------
__global__ __launch_bounds__(256) void transpose_k(
    const float* __restrict__ S, float* __restrict__ D, int R, int C)
{
    __shared__ float t[32][33];
    int c0 = blockIdx.x * 32, r0 = blockIdx.y * 32;
    int x = threadIdx.x & 31, y = threadIdx.x >> 5;   // 32 x 8
#pragma unroll
    for (int i = 0; i < 32; i += 8) {
        int r = r0 + y + i, c = c0 + x;
        t[y + i][x] = (r < R && c < C) ? S[(size_t)r * C + c] : 0.0f;
    }
    __syncthreads();
#pragma unroll
    for (int i = 0; i < 32; i += 8) {
        int r = c0 + y + i, c = r0 + x;
        if (r < C && c < R) D[(size_t)r * R + c] = t[x][y + i];
    }
}

// ---------------------------------------------------------------------------
// TF32 tensor-core GEMM via mma.sync (sm_80+ path, works on plain sm_103):
//   C(M,Nn) = A(M,Kd) * Bt(Nn,Kd)^T, fp32 in/out, TF32 multiply.
// 128x128 CTA tile, 256 threads (8 warps, 4x2), warp tile 32x64,
// K-chunk 32, single SMEM buffer, register-staged prefetch.
// Requires: M % 128 == 0, Kd % 32 == 0, Nn % 2 == 0.
// ---------------------------------------------------------------------------
#define GKC 32
#define APITCH 36   // 32 + 4 pad (floats)

__device__ __forceinline__ uint32_t f2tf(float f) {
    uint32_t u;
    asm("cvt.rna.tf32.f32 %0, %1;" : "=r"(u) : "f"(f));
    return u;
}

__device__ __forceinline__ void mma_tf32(float* c4, const uint32_t* a4,
                                         const uint32_t* b2) {
    asm volatile(
        "mma.sync.aligned.m16n8k8.row.col.f32.tf32.tf32.f32 "
        "{%0,%1,%2,%3}, {%4,%5,%6,%7}, {%8,%9}, {%0,%1,%2,%3};"
        : "+f"(c4[0]), "+f"(c4[1]), "+f"(c4[2]), "+f"(c4[3])
        : "r"(a4[0]), "r"(a4[1]), "r"(a4[2]), "r"(a4[3]),
          "r"(b2[0]), "r"(b2[1]));
}

__global__ __launch_bounds__(256, 1) void gemm_mma(
    const float* __restrict__ A, const float* __restrict__ Bt,
    float* __restrict__ C, int M, int Nn, int Kd)
{
    __shared__ float Asf[128 * APITCH];
    __shared__ float Bsf[128 * APITCH];

    const int tid = threadIdx.x;
    const int wid = tid >> 5, lane = tid & 31;
    const int gid = lane >> 2, tig = lane & 3;
    const int wm = (wid >> 1) * 32;      // warp row offset in tile
    const int wn = (wid & 1) * 64;       // warp col offset in tile
    const int row0 = blockIdx.y * 128;
    const int col0 = blockIdx.x * 128;

    float acc[2][8][4];
#pragma unroll
    for (int mi = 0; mi < 2; ++mi)
#pragma unroll
        for (int ni = 0; ni < 8; ++ni)
#pragma unroll
            for (int q = 0; q < 4; ++q) acc[mi][ni][q] = 0.0f;

    const int NCH = Kd / GKC;
    float4 sa[4], sb[4];

    // prologue: load chunk 0
#pragma unroll
    for (int i = 0; i < 4; ++i) {
        int idx = i * 256 + tid;
        int row = idx >> 3, seg = idx & 7;
        sa[i] = *(const float4*)(A + (size_t)(row0 + row) * Kd + seg * 4);
        int nr = col0 + row;
        sb[i] = (nr < Nn) ? *(const float4*)(Bt + (size_t)nr * Kd + seg * 4)
                          : make_float4(0.f, 0.f, 0.f, 0.f);
    }
#pragma unroll
    for (int i = 0; i < 4; ++i) {
        int idx = i * 256 + tid;
        int row = idx >> 3, seg = idx & 7;
        int addr = row * APITCH + seg * 4;
        uint4 ua = make_uint4(f2tf(sa[i].x), f2tf(sa[i].y), f2tf(sa[i].z), f2tf(sa[i].w));
        uint4 ub = make_uint4(f2tf(sb[i].x), f2tf(sb[i].y), f2tf(sb[i].z), f2tf(sb[i].w));
        *(uint4*)&Asf[addr] = ua;
        *(uint4*)&Bsf[addr] = ub;
    }
    __syncthreads();

    const uint32_t* Au = (const uint32_t*)Asf;
    const uint32_t* Bu = (const uint32_t*)Bsf;

    for (int c = 0; c < NCH; ++c) {
        // prefetch chunk c+1 into regs (overlaps with mma below)
        if (c + 1 < NCH) {
            int k0 = (c + 1) * GKC;
#pragma unroll
            for (int i = 0; i < 4; ++i) {
                int idx = i * 256 + tid;
                int row = idx >> 3, seg = idx & 7;
                sa[i] = *(const float4*)(A + (size_t)(row0 + row) * Kd + k0 + seg * 4);
                int nr = col0 + row;
                sb[i] = (nr < Nn)
                      ? *(const float4*)(Bt + (size_t)nr * Kd + k0 + seg * 4)
                      : make_float4(0.f, 0.f, 0.f, 0.f);
            }
        }

        // compute current chunk: 4 k-steps of 8
#pragma unroll
        for (int kk = 0; kk < 4; ++kk) {
            int kb = kk * 8;
            uint32_t af[2][4];
#pragma unroll
            for (int mi = 0; mi < 2; ++mi) {
                int base = (wm + mi * 16 + gid) * APITCH + kb + tig;
                af[mi][0] = Au[base];
                af[mi][1] = Au[base + 8 * APITCH];
                af[mi][2] = Au[base + 4];
                af[mi][3] = Au[base + 8 * APITCH + 4];
            }
            uint32_t bf[8][2];
#pragma unroll
            for (int ni = 0; ni < 8; ++ni) {
                int base = (wn + ni * 8 + gid) * APITCH + kb + tig;
                bf[ni][0] = Bu[base];
                bf[ni][1] = Bu[base + 4];
            }
#pragma unroll
            for (int mi = 0; mi < 2; ++mi)
#pragma unroll
                for (int ni = 0; ni < 8; ++ni)
                    mma_tf32(acc[mi][ni], af[mi], bf[ni]);
        }
        __syncthreads();

        if (c + 1 < NCH) {
#pragma unroll
            for (int i = 0; i < 4; ++i) {
                int idx = i * 256 + tid;
                int row = idx >> 3, seg = idx & 7;
                int addr = row * APITCH + seg * 4;
                uint4 ua = make_uint4(f2tf(sa[i].x), f2tf(sa[i].y), f2tf(sa[i].z), f2tf(sa[i].w));
                uint4 ub = make_uint4(f2tf(sb[i].x), f2tf(sb[i].y), f2tf(sb[i].z), f2tf(sb[i].w));
                *(uint4*)&Asf[addr] = ua;
                *(uint4*)&Bsf[addr] = ub;
            }
            __syncthreads();
        }
    }

    // epilogue
#pragma unroll
    for (int mi = 0; mi < 2; ++mi) {
        int r0 = row0 + wm + mi * 16 + gid;
#pragma unroll
        for (int ni = 0; ni < 8; ++ni) {
            int cc = col0 + wn + ni * 8 + tig * 2;
            if (cc < Nn) {
                *(float2*)(C + (size_t)r0 * Nn + cc) =
                    make_float2(acc[mi][ni][0], acc[mi][ni][1]);
                *(float2*)(C + (size_t)(r0 + 8) * Nn + cc) =
                    make_float2(acc[mi][ni][2], acc[mi][ni][3]);
            }
        }
    }
}

// ---------------------------------------------------------------------------
// Causal depthwise conv1d, kernel 4, left pad 3.
// ---------------------------------------------------------------------------
__global__ __launch_bounds__(256) void conv_kernel(
    const float* __restrict__ z, const float* __restrict__ wc,
    const float* __restrict__ bc, float* __restrict__ zc)
{
    int idx = blockIdx.x * 256 + threadIdx.x;
    const int total = BB * LL * TOT;
    if (idx >= total) return;
    int c  = idx % TOT;
    int bl = idx / TOT;
    int l  = bl % LL;

    float acc = bc[c];
#pragma unroll
    for (int jk = 0; jk < CONVK; ++jk) {
        int ls = l - 3 + jk;
        if (ls >= 0)
            acc += wc[jk * TOT + c] * z[(size_t)(bl - 3 + jk) * TOT + c];
    }
    zc[idx] = acc;
}

// ---------------------------------------------------------------------------
// Fused scan kernel (unchanged from passing R1 version).
// ---------------------------------------------------------------------------
__global__ __launch_bounds__(128) void scan_kernel(
    const float* __restrict__ zc, const float* __restrict__ theta,
    const float* __restrict__ dslopes, const float* __restrict__ aslopes,
    const float* __restrict__ sscale, const float* __restrict__ dlogits,
    const float* __restrict__ nscale, const float* __restrict__ W_re,
    const float* __restrict__ W_im, float* __restrict__ g_out)
{
    extern __shared__ float sm[];
    float* Wre_s = sm;                 // 4096
    float* Wim_s = sm + 4096;          // 4096
    float* sre   = sm + 8192;          // 128*12
    float* sim   = sm + 9728;          // 128*12
    float* ssq   = sm + 11264;         // 8*128
    float* sxv   = sm + 12288;         // 8*32
    float* sgv   = sm + 12544;         // 8*32
    float* ssv   = sm + 12800;         // 8
    float* srsq  = sm + 12808;         // 8
    float* ypart = sm + 12816;         // 4*8*32

    const int blk = blockIdx.x;
    const int bb  = blk >> 5;
    const int k   = blk & 31;
    const int tid = threadIdx.x;
    const int j   = tid;
    const int h   = j >> 2;
    const int lane = tid & 31;
    const int warp = tid >> 5;
    const int c  = warp;
    const int hp = lane;

    const float theta_t = theta[k * (HD * MT) + j];
    const float ns_re = nscale[j];
    const float ns_im = nscale[HD * MT + j];

    float dl0 = dlogits[0], dl1 = dlogits[1], dl2 = dlogits[2];
    float mx = fmaxf(dl0, fmaxf(dl1, dl2));
    float e0 = __expf(dl0 - mx), e1 = __expf(dl1 - mx), e2 = __expf(dl2 - mx);
    float dinv = 1.0f / (e0 + e1 + e2);
    const float w0 = e0 * dinv, w1 = e1 * dinv, w2 = e2 * dinv;

    const float ss = sscale[k];
    const bool decay = (k < KH - ANCHOR);
    const float slope = decay ? dslopes[k] : aslopes[k - (KH - ANCHOR)];
    const float rate = logf(1.0f + expf(slope));

    for (int i = tid; i < HD * MT * HD; i += 128) {
        Wre_s[i] = W_re[i];
        Wim_s[i] = W_im[i];
    }

    float accRe = 0.0f, accIm = 0.0f, accDen = 0.0f;
    const size_t baserow = (size_t)bb * LL;

    for (int l0 = 0; l0 < LL; l0 += TT) {
        __syncthreads();
        {
            int v = tid;
            int t = v >> 5, hh = v & 31;
            size_t rowA = (baserow + l0 + t) * (size_t)TOT;
            sxv[v] = zc[rowA + (size_t)k * HD + hh];
            sgv[v] = zc[rowA + DM + (size_t)k * HD + hh];
            v = tid + 128;
            t = v >> 5; hh = v & 31;
            size_t rowB = (baserow + l0 + t) * (size_t)TOT;
            sxv[v] = zc[rowB + (size_t)k * HD + hh];
            sgv[v] = zc[rowB + DM + (size_t)k * HD + hh];
            if (tid < TT)
                ssv[tid] = zc[(baserow + l0 + tid) * (size_t)TOT + 2 * DM + k];
        }
        __syncthreads();

#pragma unroll
        for (int t = 0; t < TT; ++t) {
            int l = l0 + t;
            float xv = sxv[t * 32 + h];
            float sv = ssv[t];
            float parg = fminf(fmaxf(ss * sv, -20.0f), 20.0f);
            float p = __expf(parg);
            float tw = decay ? __expf(-rate * (float)(LL - 1 - l))
                             : __expf(-rate * (float)l);
            float pw = p * tw;
            float phi = xv * theta_t;
            float sbv, cbv;
            __sincosf(phi, &sbv, &cbv);
            float poly = w0 + w1 * xv - w2 * xv * xv;
            float ppw = pw * poly;
            accDen += pw;
            accRe  += ppw * cbv;
            accIm  += ppw * sbv;
            float invd = 1.0f / fmaxf(accDen, 1e-4f);
            float re = accRe * invd;
            float im = accIm * invd;
            sre[j * 12 + t] = re;
            sim[j * 12 + t] = im;
            ssq[t * 128 + j] = re * re + im * im;
        }
        __syncthreads();

        {
            int tt = warp * 2;
#pragma unroll
            for (int q = 0; q < 2; ++q, ++tt) {
                float v = ssq[tt * 128 + lane] + ssq[tt * 128 + lane + 32]
                        + ssq[tt * 128 + lane + 64] + ssq[tt * 128 + lane + 96];
#pragma unroll
                for (int off = 16; off; off >>= 1)
                    v += __shfl_xor_sync(0xffffffffu, v, off);
                if (lane == 0)
                    srsq[tt] = rsqrtf(v * (1.0f / (2.0f * HD * MT)) + 1e-5f);
            }
        }
        __syncthreads();

#pragma unroll
        for (int t = 0; t < TT; ++t) {
            float r = srsq[t];
            sre[j * 12 + t] *= r * ns_re;
            sim[j * 12 + t] *= r * ns_im;
        }
        __syncthreads();

        float acc[TT];
#pragma unroll
        for (int t = 0; t < TT; ++t) acc[t] = 0.0f;
#pragma unroll 8
        for (int jj = 0; jj < 32; ++jj) {
            int jg = c * 32 + jj;
            float wr = Wre_s[jg * 32 + hp];
            float wi = Wim_s[jg * 32 + hp];
            float4 r0 = *(const float4*)(sre + jg * 12);
            float4 r1 = *(const float4*)(sre + jg * 12 + 4);
            float4 i0 = *(const float4*)(sim + jg * 12);
            float4 i1 = *(const float4*)(sim + jg * 12 + 4);
            acc[0] += r0.x * wr + i0.x * wi;
            acc[1] += r0.y * wr + i0.y * wi;
            acc[2] += r0.z * wr + i0.z * wi;
            acc[3] += r0.w * wr + i0.w * wi;
            acc[4] += r1.x * wr + i1.x * wi;
            acc[5] += r1.y * wr + i1.y * wi;
            acc[6] += r1.z * wr + i1.z * wi;
            acc[7] += r1.w * wr + i1.w * wi;
        }
#pragma unroll
        for (int t = 0; t < TT; ++t)
            ypart[(c * TT + t) * 32 + hp] = acc[t];
        __syncthreads();

        for (int v = tid; v < TT * 32; v += 128) {
            int t = v >> 5, hh = v & 31;
            float y = ypart[t * 32 + hh] + ypart[(TT + t) * 32 + hh]
                    + ypart[(2 * TT + t) * 32 + hh] + ypart[(3 * TT + t) * 32 + hh];
            float gz = sgv[t * 32 + hh];
            float gate = gz / (1.0f + __expf(-gz));
            g_out[(baserow + l0 + t) * (size_t)DM + (size_t)k * HD + hh] = y * gate;
        }
    }
}

// ---------------------------------------------------------------------------
extern "C" void kernel_launch(void* const* d_in, const int* in_sizes, int n_in,
                              void* d_out, int out_size)
{
    const float* x       = (const float*)d_in[0];
    const float* W_in    = (const float*)d_in[1];
    const float* w_conv  = (const float*)d_in[2];
    const float* b_conv  = (const float*)d_in[3];
    const float* theta   = (const float*)d_in[4];
    const float* dslopes = (const float*)d_in[5];
    const float* aslopes = (const float*)d_in[6];
    const float* sscale  = (const float*)d_in[7];
    const float* dlogits = (const float*)d_in[8];
    const float* nscale  = (const float*)d_in[9];
    const float* W_re    = (const float*)d_in[10];
    const float* W_im    = (const float*)d_in[11];
    const float* W_out   = (const float*)d_in[12];
    float* out = (float*)d_out;

    float *pz, *pzc, *pg, *pbt1, *pbt2;
    cudaGetSymbolAddress((void**)&pz,   g_z);
    cudaGetSymbolAddress((void**)&pzc,  g_zc);
    cudaGetSymbolAddress((void**)&pg,   g_g);
    cudaGetSymbolAddress((void**)&pbt1, g_bt1);
    cudaGetSymbolAddress((void**)&pbt2, g_bt2);

    static bool attr_set = false;
    if (!attr_set) {
        cudaFuncSetAttribute(scan_kernel,
                             cudaFuncAttributeMaxDynamicSharedMemorySize, 56 * 1024);
        attr_set = true;
    }

    // 0) transpose weights to K-major (N x K)
    transpose_k<<<dim3((TOT + 31) / 32, DM / 32), 256>>>(W_in, pbt1, DM, TOT);
    transpose_k<<<dim3(DM / 32, DM / 32), 256>>>(W_out, pbt2, DM, DM);

    // 1) z = x @ W_in   (8192 x 2080, K=1024)  — TF32 mma.sync
    {
        dim3 grid((TOT + 127) / 128, (BB * LL) / 128);
        gemm_mma<<<grid, 256>>>(x, pbt1, pz, BB * LL, TOT, DM);
    }
    // 2) causal depthwise conv
    {
        int total = BB * LL * TOT;
        conv_kernel<<<(total + 255) / 256, 256>>>(pz, w_conv, b_conv, pzc);
    }
    // 3) fused scan + norm + head projection + gate
    scan_kernel<<<BB * KH, 128, 55360>>>(pzc, theta, dslopes, aslopes,
                                         sscale, dlogits, nscale,
                                         W_re, W_im, pg);
    // 4) out = g @ W_out  (8192 x 1024, K=1024) — TF32 mma.sync
    {
        dim3 grid(DM / 128, (BB * LL) / 128);
        gemm_mma<<<grid, 256>>>(pg, pbt2, out, BB * LL, DM, DM);
    }
}

// round 4
// speedup vs baseline: 2.5302x; 1.5359x over previous
#include <cuda_runtime.h>
#include <cuda_bf16.h>
#include <cstdint>

// Problem constants
#define BB   4
#define LL   2048
#define DM   1024
#define KH   32        // heads
#define HD   32        // head dim
#define MT   4         // m_theta
#define TOT  2080      // 2*DM + KH
#define CONVK 4
#define ANCHOR 4
#define TT   8         // scan tile (time steps per tile)
#define NC   32        // scan chunks
#define CL   (LL / NC) // 64 steps per chunk

// Scratch (static device globals — no runtime allocation allowed)
__device__ float g_z   [BB * LL * TOT];   // x @ W_in
__device__ float g_zc  [BB * LL * TOT];   // after causal depthwise conv
__device__ float g_g   [BB * LL * DM];    // gated y (input to final GEMM)
__device__ float g_bt1 [TOT * DM];        // W_in^T  (2080 x 1024), K-major rows
__device__ float g_bt2 [DM * DM];         // W_out^T (1024 x 1024)
__device__ float g_part[BB * KH * NC * 3 * 128];  // chunk partials / prefixes

// ---------------------------------------------------------------------------
// Tiled transpose: D[C][R] = S[R][C]^T
// ---------------------------------------------------------------------------
__global__ __launch_bounds__(256) void transpose_k(
    const float* __restrict__ S, float* __restrict__ D, int R, int C)
{
    __shared__ float t[32][33];
    int c0 = blockIdx.x * 32, r0 = blockIdx.y * 32;
    int x = threadIdx.x & 31, y = threadIdx.x >> 5;   // 32 x 8
#pragma unroll
    for (int i = 0; i < 32; i += 8) {
        int r = r0 + y + i, c = c0 + x;
        t[y + i][x] = (r < R && c < C) ? S[(size_t)r * C + c] : 0.0f;
    }
    __syncthreads();
#pragma unroll
    for (int i = 0; i < 32; i += 8) {
        int r = c0 + y + i, c = r0 + x;
        if (r < C && c < R) D[(size_t)r * R + c] = t[x][y + i];
    }
}

// ---------------------------------------------------------------------------
// TF32 tensor-core GEMM via mma.sync (unchanged from passing R3 version).
// ---------------------------------------------------------------------------
#define GKC 32
#define APITCH 36   // 32 + 4 pad (floats)

__device__ __forceinline__ uint32_t f2tf(float f) {
    uint32_t u;
    asm("cvt.rna.tf32.f32 %0, %1;" : "=r"(u) : "f"(f));
    return u;
}

__device__ __forceinline__ void mma_tf32(float* c4, const uint32_t* a4,
                                         const uint32_t* b2) {
    asm volatile(
        "mma.sync.aligned.m16n8k8.row.col.f32.tf32.tf32.f32 "
        "{%0,%1,%2,%3}, {%4,%5,%6,%7}, {%8,%9}, {%0,%1,%2,%3};"
        : "+f"(c4[0]), "+f"(c4[1]), "+f"(c4[2]), "+f"(c4[3])
        : "r"(a4[0]), "r"(a4[1]), "r"(a4[2]), "r"(a4[3]),
          "r"(b2[0]), "r"(b2[1]));
}

__global__ __launch_bounds__(256, 1) void gemm_mma(
    const float* __restrict__ A, const float* __restrict__ Bt,
    float* __restrict__ C, int M, int Nn, int Kd)
{
    __shared__ float Asf[128 * APITCH];
    __shared__ float Bsf[128 * APITCH];

    const int tid = threadIdx.x;
    const int wid = tid >> 5, lane = tid & 31;
    const int gid = lane >> 2, tig = lane & 3;
    const int wm = (wid >> 1) * 32;
    const int wn = (wid & 1) * 64;
    const int row0 = blockIdx.y * 128;
    const int col0 = blockIdx.x * 128;

    float acc[2][8][4];
#pragma unroll
    for (int mi = 0; mi < 2; ++mi)
#pragma unroll
        for (int ni = 0; ni < 8; ++ni)
#pragma unroll
            for (int q = 0; q < 4; ++q) acc[mi][ni][q] = 0.0f;

    const int NCH = Kd / GKC;
    float4 sa[4], sb[4];

#pragma unroll
    for (int i = 0; i < 4; ++i) {
        int idx = i * 256 + tid;
        int row = idx >> 3, seg = idx & 7;
        sa[i] = *(const float4*)(A + (size_t)(row0 + row) * Kd + seg * 4);
        int nr = col0 + row;
        sb[i] = (nr < Nn) ? *(const float4*)(Bt + (size_t)nr * Kd + seg * 4)
                          : make_float4(0.f, 0.f, 0.f, 0.f);
    }
#pragma unroll
    for (int i = 0; i < 4; ++i) {
        int idx = i * 256 + tid;
        int row = idx >> 3, seg = idx & 7;
        int addr = row * APITCH + seg * 4;
        uint4 ua = make_uint4(f2tf(sa[i].x), f2tf(sa[i].y), f2tf(sa[i].z), f2tf(sa[i].w));
        uint4 ub = make_uint4(f2tf(sb[i].x), f2tf(sb[i].y), f2tf(sb[i].z), f2tf(sb[i].w));
        *(uint4*)&Asf[addr] = ua;
        *(uint4*)&Bsf[addr] = ub;
    }
    __syncthreads();

    const uint32_t* Au = (const uint32_t*)Asf;
    const uint32_t* Bu = (const uint32_t*)Bsf;

    for (int c = 0; c < NCH; ++c) {
        if (c + 1 < NCH) {
            int k0 = (c + 1) * GKC;
#pragma unroll
            for (int i = 0; i < 4; ++i) {
                int idx = i * 256 + tid;
                int row = idx >> 3, seg = idx & 7;
                sa[i] = *(const float4*)(A + (size_t)(row0 + row) * Kd + k0 + seg * 4);
                int nr = col0 + row;
                sb[i] = (nr < Nn)
                      ? *(const float4*)(Bt + (size_t)nr * Kd + k0 + seg * 4)
                      : make_float4(0.f, 0.f, 0.f, 0.f);
            }
        }

#pragma unroll
        for (int kk = 0; kk < 4; ++kk) {
            int kb = kk * 8;
            uint32_t af[2][4];
#pragma unroll
            for (int mi = 0; mi < 2; ++mi) {
                int base = (wm + mi * 16 + gid) * APITCH + kb + tig;
                af[mi][0] = Au[base];
                af[mi][1] = Au[base + 8 * APITCH];
                af[mi][2] = Au[base + 4];
                af[mi][3] = Au[base + 8 * APITCH + 4];
            }
            uint32_t bf[8][2];
#pragma unroll
            for (int ni = 0; ni < 8; ++ni) {
                int base = (wn + ni * 8 + gid) * APITCH + kb + tig;
                bf[ni][0] = Bu[base];
                bf[ni][1] = Bu[base + 4];
            }
#pragma unroll
            for (int mi = 0; mi < 2; ++mi)
#pragma unroll
                for (int ni = 0; ni < 8; ++ni)
                    mma_tf32(acc[mi][ni], af[mi], bf[ni]);
        }
        __syncthreads();

        if (c + 1 < NCH) {
#pragma unroll
            for (int i = 0; i < 4; ++i) {
                int idx = i * 256 + tid;
                int row = idx >> 3, seg = idx & 7;
                int addr = row * APITCH + seg * 4;
                uint4 ua = make_uint4(f2tf(sa[i].x), f2tf(sa[i].y), f2tf(sa[i].z), f2tf(sa[i].w));
                uint4 ub = make_uint4(f2tf(sb[i].x), f2tf(sb[i].y), f2tf(sb[i].z), f2tf(sb[i].w));
                *(uint4*)&Asf[addr] = ua;
                *(uint4*)&Bsf[addr] = ub;
            }
            __syncthreads();
        }
    }

#pragma unroll
    for (int mi = 0; mi < 2; ++mi) {
        int r0 = row0 + wm + mi * 16 + gid;
#pragma unroll
        for (int ni = 0; ni < 8; ++ni) {
            int cc = col0 + wn + ni * 8 + tig * 2;
            if (cc < Nn) {
                *(float2*)(C + (size_t)r0 * Nn + cc) =
                    make_float2(acc[mi][ni][0], acc[mi][ni][1]);
                *(float2*)(C + (size_t)(r0 + 8) * Nn + cc) =
                    make_float2(acc[mi][ni][2], acc[mi][ni][3]);
            }
        }
    }
}

// ---------------------------------------------------------------------------
// Causal depthwise conv1d, kernel 4, left pad 3.
// ---------------------------------------------------------------------------
__global__ __launch_bounds__(256) void conv_kernel(
    const float* __restrict__ z, const float* __restrict__ wc,
    const float* __restrict__ bc, float* __restrict__ zc)
{
    int idx = blockIdx.x * 256 + threadIdx.x;
    const int total = BB * LL * TOT;
    if (idx >= total) return;
    int c  = idx % TOT;
    int bl = idx / TOT;
    int l  = bl % LL;

    float acc = bc[c];
#pragma unroll
    for (int jk = 0; jk < CONVK; ++jk) {
        int ls = l - 3 + jk;
        if (ls >= 0)
            acc += wc[jk * TOT + c] * z[(size_t)(bl - 3 + jk) * TOT + c];
    }
    zc[idx] = acc;
}

// ---------------------------------------------------------------------------
// Shared per-thread scan preamble (computed per block; k = head index)
// ---------------------------------------------------------------------------
struct ScanConst {
    float theta_t, w0, w1, w2, ss, rate;
    bool decay;
};

__device__ __forceinline__ ScanConst scan_consts(
    int k, int j, const float* theta, const float* dslopes,
    const float* aslopes, const float* sscale, const float* dlogits)
{
    ScanConst sc;
    sc.theta_t = theta[k * (HD * MT) + j];
    float dl0 = dlogits[0], dl1 = dlogits[1], dl2 = dlogits[2];
    float mx = fmaxf(dl0, fmaxf(dl1, dl2));
    float e0 = __expf(dl0 - mx), e1 = __expf(dl1 - mx), e2 = __expf(dl2 - mx);
    float dinv = 1.0f / (e0 + e1 + e2);
    sc.w0 = e0 * dinv; sc.w1 = e1 * dinv; sc.w2 = e2 * dinv;
    sc.ss = sscale[k];
    sc.decay = (k < KH - ANCHOR);
    float slope = sc.decay ? dslopes[k] : aslopes[k - (KH - ANCHOR)];
    sc.rate = logf(1.0f + expf(slope));
    return sc;
}

__device__ __forceinline__ void scan_step(
    const ScanConst& sc, float xv, float sv, int l,
    float& accRe, float& accIm, float& accDen)
{
    float parg = fminf(fmaxf(sc.ss * sv, -20.0f), 20.0f);
    float p = __expf(parg);
    float tw = sc.decay ? __expf(-sc.rate * (float)(LL - 1 - l))
                        : __expf(-sc.rate * (float)l);
    float pw = p * tw;
    float phi = xv * sc.theta_t;
    float sbv, cbv;
    __sincosf(phi, &sbv, &cbv);
    float poly = sc.w0 + sc.w1 * xv - sc.w2 * xv * xv;
    float ppw = pw * poly;
    accDen += pw;
    accRe  += ppw * cbv;
    accIm  += ppw * sbv;
}

// ---------------------------------------------------------------------------
// Scan pass 1: per-chunk lane sums. grid = B*K*NC, block = 128.
// blockIdx.x = (bb*KH + k)*NC + chunk.
// part layout: [(bk*NC + chunk)*3*128] : [Re 128][Im 128][Den 128]
// ---------------------------------------------------------------------------
__global__ __launch_bounds__(128) void scan_part1(
    const float* __restrict__ zc, const float* __restrict__ theta,
    const float* __restrict__ dslopes, const float* __restrict__ aslopes,
    const float* __restrict__ sscale, const float* __restrict__ dlogits,
    float* __restrict__ part)
{
    __shared__ float sxv[TT * 32];
    __shared__ float ssv[TT];

    const int chunk = blockIdx.x % NC;
    const int bk    = blockIdx.x / NC;
    const int k  = bk % KH;
    const int bb = bk / KH;
    const int tid = threadIdx.x;
    const int j = tid, h = j >> 2;

    const ScanConst sc = scan_consts(k, j, theta, dslopes, aslopes, sscale, dlogits);

    float accRe = 0.0f, accIm = 0.0f, accDen = 0.0f;
    const size_t baserow = (size_t)bb * LL;

    for (int l0 = chunk * CL; l0 < chunk * CL + CL; l0 += TT) {
        __syncthreads();
        {
            int v = tid;
            int t = v >> 5, hh = v & 31;
            sxv[v] = zc[(baserow + l0 + t) * (size_t)TOT + (size_t)k * HD + hh];
            v = tid + 128; t = v >> 5; hh = v & 31;
            sxv[v] = zc[(baserow + l0 + t) * (size_t)TOT + (size_t)k * HD + hh];
            if (tid < TT)
                ssv[tid] = zc[(baserow + l0 + tid) * (size_t)TOT + 2 * DM + k];
        }
        __syncthreads();
#pragma unroll
        for (int t = 0; t < TT; ++t)
            scan_step(sc, sxv[t * 32 + h], ssv[t], l0 + t, accRe, accIm, accDen);
    }

    float* p = part + (size_t)blockIdx.x * 384;
    p[j] = accRe; p[128 + j] = accIm; p[256 + j] = accDen;
}

// ---------------------------------------------------------------------------
// Scan pass 2: exclusive prefix over chunks, in place. grid = B*K, block 128.
// ---------------------------------------------------------------------------
__global__ __launch_bounds__(128) void scan_part2(float* __restrict__ part)
{
    const int bk = blockIdx.x;
    const int j = threadIdx.x;
    float rRe = 0.0f, rIm = 0.0f, rDen = 0.0f;
    for (int c = 0; c < NC; ++c) {
        float* p = part + ((size_t)bk * NC + c) * 384;
        float tRe = p[j], tIm = p[128 + j], tDen = p[256 + j];
        p[j] = rRe; p[128 + j] = rIm; p[256 + j] = rDen;
        rRe += tRe; rIm += tIm; rDen += tDen;
    }
}

// ---------------------------------------------------------------------------
// Scan pass 3: full scan over chunk with prefix seed + RMS norm + projection
// + gate. grid = B*K*NC, block = 128.
// ---------------------------------------------------------------------------
__global__ __launch_bounds__(128) void scan_part3(
    const float* __restrict__ zc, const float* __restrict__ theta,
    const float* __restrict__ dslopes, const float* __restrict__ aslopes,
    const float* __restrict__ sscale, const float* __restrict__ dlogits,
    const float* __restrict__ nscale, const float* __restrict__ W_re,
    const float* __restrict__ W_im, const float* __restrict__ part,
    float* __restrict__ g_out)
{
    extern __shared__ float sm[];
    float* Wre_s = sm;                 // 4096
    float* Wim_s = sm + 4096;          // 4096
    float* sre   = sm + 8192;          // 128*12
    float* sim   = sm + 9728;          // 128*12
    float* ssq   = sm + 11264;         // 8*128
    float* sxv   = sm + 12288;         // 8*32
    float* sgv   = sm + 12544;         // 8*32
    float* ssv   = sm + 12800;         // 8
    float* srsq  = sm + 12808;         // 8
    float* ypart = sm + 12816;         // 4*8*32

    const int chunk = blockIdx.x % NC;
    const int bk    = blockIdx.x / NC;
    const int k  = bk % KH;
    const int bb = bk / KH;
    const int tid = threadIdx.x;
    const int j = tid, h = j >> 2;
    const int lane = tid & 31;
    const int warp = tid >> 5;
    const int c  = warp;
    const int hp = lane;

    const ScanConst sc = scan_consts(k, j, theta, dslopes, aslopes, sscale, dlogits);
    const float ns_re = nscale[j];
    const float ns_im = nscale[HD * MT + j];

    for (int i = tid; i < HD * MT * HD; i += 128) {
        Wre_s[i] = W_re[i];
        Wim_s[i] = W_im[i];
    }

    const float* pfx = part + (size_t)blockIdx.x * 384;
    float accRe = pfx[j], accIm = pfx[128 + j], accDen = pfx[256 + j];
    const size_t baserow = (size_t)bb * LL;

    for (int l0 = chunk * CL; l0 < chunk * CL + CL; l0 += TT) {
        __syncthreads();
        {
            int v = tid;
            int t = v >> 5, hh = v & 31;
            size_t rowA = (baserow + l0 + t) * (size_t)TOT;
            sxv[v] = zc[rowA + (size_t)k * HD + hh];
            sgv[v] = zc[rowA + DM + (size_t)k * HD + hh];
            v = tid + 128; t = v >> 5; hh = v & 31;
            size_t rowB = (baserow + l0 + t) * (size_t)TOT;
            sxv[v] = zc[rowB + (size_t)k * HD + hh];
            sgv[v] = zc[rowB + DM + (size_t)k * HD + hh];
            if (tid < TT)
                ssv[tid] = zc[(baserow + l0 + tid) * (size_t)TOT + 2 * DM + k];
        }
        __syncthreads();

#pragma unroll
        for (int t = 0; t < TT; ++t) {
            scan_step(sc, sxv[t * 32 + h], ssv[t], l0 + t, accRe, accIm, accDen);
            float invd = 1.0f / fmaxf(accDen, 1e-4f);
            float re = accRe * invd;
            float im = accIm * invd;
            sre[j * 12 + t] = re;
            sim[j * 12 + t] = im;
            ssq[t * 128 + j] = re * re + im * im;
        }
        __syncthreads();

        {
            int tt = warp * 2;
#pragma unroll
            for (int q = 0; q < 2; ++q, ++tt) {
                float v = ssq[tt * 128 + lane] + ssq[tt * 128 + lane + 32]
                        + ssq[tt * 128 + lane + 64] + ssq[tt * 128 + lane + 96];
#pragma unroll
                for (int off = 16; off; off >>= 1)
                    v += __shfl_xor_sync(0xffffffffu, v, off);
                if (lane == 0)
                    srsq[tt] = rsqrtf(v * (1.0f / (2.0f * HD * MT)) + 1e-5f);
            }
        }
        __syncthreads();

#pragma unroll
        for (int t = 0; t < TT; ++t) {
            float r = srsq[t];
            sre[j * 12 + t] *= r * ns_re;
            sim[j * 12 + t] *= r * ns_im;
        }
        __syncthreads();

        float acc[TT];
#pragma unroll
        for (int t = 0; t < TT; ++t) acc[t] = 0.0f;
#pragma unroll 8
        for (int jj = 0; jj < 32; ++jj) {
            int jg = c * 32 + jj;
            float wr = Wre_s[jg * 32 + hp];
            float wi = Wim_s[jg * 32 + hp];
            float4 r0 = *(const float4*)(sre + jg * 12);
            float4 r1 = *(const float4*)(sre + jg * 12 + 4);
            float4 i0 = *(const float4*)(sim + jg * 12);
            float4 i1 = *(const float4*)(sim + jg * 12 + 4);
            acc[0] += r0.x * wr + i0.x * wi;
            acc[1] += r0.y * wr + i0.y * wi;
            acc[2] += r0.z * wr + i0.z * wi;
            acc[3] += r0.w * wr + i0.w * wi;
            acc[4] += r1.x * wr + i1.x * wi;
            acc[5] += r1.y * wr + i1.y * wi;
            acc[6] += r1.z * wr + i1.z * wi;
            acc[7] += r1.w * wr + i1.w * wi;
        }
#pragma unroll
        for (int t = 0; t < TT; ++t)
            ypart[(c * TT + t) * 32 + hp] = acc[t];
        __syncthreads();

        for (int v = tid; v < TT * 32; v += 128) {
            int t = v >> 5, hh = v & 31;
            float y = ypart[t * 32 + hh] + ypart[(TT + t) * 32 + hh]
                    + ypart[(2 * TT + t) * 32 + hh] + ypart[(3 * TT + t) * 32 + hh];
            float gz = sgv[t * 32 + hh];
            float gate = gz / (1.0f + __expf(-gz));
            g_out[(baserow + l0 + t) * (size_t)DM + (size_t)k * HD + hh] = y * gate;
        }
    }
}

// ---------------------------------------------------------------------------
extern "C" void kernel_launch(void* const* d_in, const int* in_sizes, int n_in,
                              void* d_out, int out_size)
{
    const float* x       = (const float*)d_in[0];
    const float* W_in    = (const float*)d_in[1];
    const float* w_conv  = (const float*)d_in[2];
    const float* b_conv  = (const float*)d_in[3];
    const float* theta   = (const float*)d_in[4];
    const float* dslopes = (const float*)d_in[5];
    const float* aslopes = (const float*)d_in[6];
    const float* sscale  = (const float*)d_in[7];
    const float* dlogits = (const float*)d_in[8];
    const float* nscale  = (const float*)d_in[9];
    const float* W_re    = (const float*)d_in[10];
    const float* W_im    = (const float*)d_in[11];
    const float* W_out   = (const float*)d_in[12];
    float* out = (float*)d_out;

    float *pz, *pzc, *pg, *pbt1, *pbt2, *ppart;
    cudaGetSymbolAddress((void**)&pz,    g_z);
    cudaGetSymbolAddress((void**)&pzc,   g_zc);
    cudaGetSymbolAddress((void**)&pg,    g_g);
    cudaGetSymbolAddress((void**)&pbt1,  g_bt1);
    cudaGetSymbolAddress((void**)&pbt2,  g_bt2);
    cudaGetSymbolAddress((void**)&ppart, g_part);

    static bool attr_set = false;
    if (!attr_set) {
        cudaFuncSetAttribute(scan_part3,
                             cudaFuncAttributeMaxDynamicSharedMemorySize, 56 * 1024);
        attr_set = true;
    }

    // 0) transpose weights to K-major (N x K)
    transpose_k<<<dim3((TOT + 31) / 32, DM / 32), 256>>>(W_in, pbt1, DM, TOT);
    transpose_k<<<dim3(DM / 32, DM / 32), 256>>>(W_out, pbt2, DM, DM);

    // 1) z = x @ W_in   (8192 x 2080, K=1024)  — TF32 mma.sync
    {
        dim3 grid((TOT + 127) / 128, (BB * LL) / 128);
        gemm_mma<<<grid, 256>>>(x, pbt1, pz, BB * LL, TOT, DM);
    }
    // 2) causal depthwise conv
    {
        int total = BB * LL * TOT;
        conv_kernel<<<(total + 255) / 256, 256>>>(pz, w_conv, b_conv, pzc);
    }
    // 3) chunked parallel scan (3 passes)
    scan_part1<<<BB * KH * NC, 128>>>(pzc, theta, dslopes, aslopes,
                                      sscale, dlogits, ppart);
    scan_part2<<<BB * KH, 128>>>(ppart);
    scan_part3<<<BB * KH * NC, 128, 55360>>>(pzc, theta, dslopes, aslopes,
                                             sscale, dlogits, nscale,
                                             W_re, W_im, ppart, pg);
    // 4) out = g @ W_out  (8192 x 1024, K=1024) — TF32 mma.sync
    {
        dim3 grid(DM / 128, (BB * LL) / 128);
        gemm_mma<<<grid, 256>>>(pg, pbt2, out, BB * LL, DM, DM);
    }
}

// round 5
// speedup vs baseline: 3.0354x; 1.1997x over previous
#include <cuda_runtime.h>
#include <cuda_bf16.h>
#include <cstdint>

// Problem constants
#define BB   4
#define LL   2048
#define DM   1024
#define KH   32        // heads
#define HD   32        // head dim
#define MT   4         // m_theta
#define TOT  2080      // 2*DM + KH
#define CONVK 4
#define ANCHOR 4
#define TT   8         // scan tile (time steps per tile)
#define NC   32        // scan chunks
#define CL   (LL / NC) // 64 steps per chunk

// Scratch (static device globals — no runtime allocation allowed)
__device__ float g_z   [BB * LL * TOT];   // x @ W_in
__device__ float g_zc  [BB * LL * TOT];   // after causal depthwise conv
__device__ float g_g   [BB * LL * DM];    // gated y (input to final GEMM), tf32-rounded
__device__ float g_x32 [BB * LL * DM];    // x rounded to tf32
__device__ float g_bt1 [TOT * DM];        // W_in^T  (2080 x 1024), K-major, tf32-rounded
__device__ float g_bt2 [DM * DM];         // W_out^T (1024 x 1024), tf32-rounded
__device__ float g_part[BB * KH * NC * 3 * 128];  // chunk partials / prefixes

// ---------------------------------------------------------------------------
// TF32 helpers
// ---------------------------------------------------------------------------
__device__ __forceinline__ uint32_t f2tf(float f) {
    uint32_t u;
    asm("cvt.rna.tf32.f32 %0, %1;" : "=r"(u) : "f"(f));
    return u;
}
__device__ __forceinline__ float f2tf_f(float f) {
    return __uint_as_float(f2tf(f));
}

__device__ __forceinline__ void mma_tf32(float* c4, const uint32_t* a4,
                                         const uint32_t* b2) {
    asm volatile(
        "mma.sync.aligned.m16n8k8.row.col.f32.tf32.tf32.f32 "
        "{%0,%1,%2,%3}, {%4,%5,%6,%7}, {%8,%9}, {%0,%1,%2,%3};"
        : "+f"(c4[0]), "+f"(c4[1]), "+f"(c4[2]), "+f"(c4[3])
        : "r"(a4[0]), "r"(a4[1]), "r"(a4[2]), "r"(a4[3]),
          "r"(b2[0]), "r"(b2[1]));
}

__device__ __forceinline__ uint32_t smem_u32(const void* p) {
    uint32_t a;
    asm("{ .reg .u64 t; cvta.to.shared.u64 t, %1; cvt.u32.u64 %0, t; }"
        : "=r"(a) : "l"(p));
    return a;
}
__device__ __forceinline__ void cpa16(uint32_t d, const void* s, int sz) {
    asm volatile("cp.async.cg.shared.global [%0], [%1], 16, %2;"
                 :: "r"(d), "l"(s), "r"(sz));
}
#define CP_COMMIT() asm volatile("cp.async.commit_group;" ::: "memory")
#define CP_WAIT1()  asm volatile("cp.async.wait_group 1;" ::: "memory")

// ---------------------------------------------------------------------------
// Round fp32 array to tf32 (RNA), vectorized. n4 = element count / 4.
// ---------------------------------------------------------------------------
__global__ __launch_bounds__(256) void round_tf32_k(
    const float4* __restrict__ src, float4* __restrict__ dst, int n4)
{
    int i = blockIdx.x * 256 + threadIdx.x;
    if (i < n4) {
        float4 v = src[i];
        v.x = f2tf_f(v.x); v.y = f2tf_f(v.y);
        v.z = f2tf_f(v.z); v.w = f2tf_f(v.w);
        dst[i] = v;
    }
}

// ---------------------------------------------------------------------------
// Tiled transpose with tf32 rounding: D[C][R] = round_tf32(S[R][C]^T)
// ---------------------------------------------------------------------------
__global__ __launch_bounds__(256) void transpose_k(
    const float* __restrict__ S, float* __restrict__ D, int R, int C)
{
    __shared__ float t[32][33];
    int c0 = blockIdx.x * 32, r0 = blockIdx.y * 32;
    int x = threadIdx.x & 31, y = threadIdx.x >> 5;   // 32 x 8
#pragma unroll
    for (int i = 0; i < 32; i += 8) {
        int r = r0 + y + i, c = c0 + x;
        t[y + i][x] = (r < R && c < C) ? S[(size_t)r * C + c] : 0.0f;
    }
    __syncthreads();
#pragma unroll
    for (int i = 0; i < 32; i += 8) {
        int r = c0 + y + i, c = r0 + x;
        if (r < C && c < R) D[(size_t)r * R + c] = f2tf_f(t[x][y + i]);
    }
}

// ---------------------------------------------------------------------------
// TF32 tensor-core GEMM, cp.async 3-stage pipeline:
//   C(M,Nn) = A(M,Kd) * Bt(Nn,Kd)^T; A and Bt must be pre-rounded to tf32.
// 128x128 CTA tile, 256 threads (8 warps 4x2), warp tile 32x64, K-chunk 32.
// SMEM: 3 stages x (A 16KB + B 16KB), XOR-swizzled 16B segments.
// Requires: M % 128 == 0, Kd % 32 == 0.
// ---------------------------------------------------------------------------
#define GKC 32
#define STAGE_BYTES 32768           // one stage: A 16384 + B 16384
#define GEMM_SMEM  (3 * STAGE_BYTES)

__global__ __launch_bounds__(256, 2) void gemm_cp(
    const float* __restrict__ A, const float* __restrict__ Bt,
    float* __restrict__ C, int M, int Nn, int Kd)
{
    extern __shared__ float smem[];
    const uint32_t sbase = smem_u32(smem);
    const int tid = threadIdx.x;
    const int wid = tid >> 5, lane = tid & 31;
    const int gid = lane >> 2, tig = lane & 3;
    const int wm = (wid >> 1) * 32;
    const int wn = (wid & 1) * 64;
    const int row0 = blockIdx.y * 128;
    const int col0 = blockIdx.x * 128;
    const int NCH = Kd / GKC;

    float acc[2][8][4];
#pragma unroll
    for (int mi = 0; mi < 2; ++mi)
#pragma unroll
        for (int ni = 0; ni < 8; ++ni)
#pragma unroll
            for (int q = 0; q < 4; ++q) acc[mi][ni][q] = 0.0f;

    // per-thread copy coords: idx = i*256+tid -> (row, 16B-seg)
    int prow[4], pseg[4];
    uint32_t poff[4];
#pragma unroll
    for (int i = 0; i < 4; ++i) {
        int idx = i * 256 + tid;
        prow[i] = idx >> 3;
        pseg[i] = idx & 7;
        poff[i] = (uint32_t)(prow[i] * 128 + ((pseg[i] ^ (prow[i] & 7)) << 4));
    }

#define PREFETCH(pc) do {                                                     \
    if ((pc) < NCH) {                                                         \
        int k0 = (pc) * GKC;                                                  \
        uint32_t stb = sbase + ((pc) % 3) * STAGE_BYTES;                      \
        _Pragma("unroll")                                                     \
        for (int i = 0; i < 4; ++i) {                                         \
            cpa16(stb + poff[i],                                              \
                  A + (size_t)(row0 + prow[i]) * Kd + k0 + pseg[i] * 4, 16);  \
            int nr = col0 + prow[i];                                          \
            int ok = (nr < Nn);                                               \
            cpa16(stb + 16384 + poff[i],                                      \
                  Bt + (size_t)(ok ? nr : 0) * Kd + k0 + pseg[i] * 4,         \
                  ok ? 16 : 0);                                               \
        }                                                                     \
    }                                                                         \
    CP_COMMIT();                                                              \
} while (0)

    PREFETCH(0);
    PREFETCH(1);

    for (int c = 0; c < NCH; ++c) {
        CP_WAIT1();
        __syncthreads();
        PREFETCH(c + 2);

        const float* Af = smem + (c % 3) * 8192;
        const float* Bf = Af + 4096;

#pragma unroll
        for (int kk = 0; kk < 4; ++kk) {
            uint32_t af[2][4];
#pragma unroll
            for (int mi = 0; mi < 2; ++mi) {
                int ra = wm + mi * 16 + gid;
                int s0 = ((kk * 2) ^ (ra & 7)) << 2;
                int s1 = ((kk * 2 + 1) ^ (ra & 7)) << 2;
                int base = ra * 32 + tig;
                af[mi][0] = __float_as_uint(Af[base + s0]);
                af[mi][1] = __float_as_uint(Af[base + s0 + 256]);
                af[mi][2] = __float_as_uint(Af[base + s1]);
                af[mi][3] = __float_as_uint(Af[base + s1 + 256]);
            }
            uint32_t bf[8][2];
#pragma unroll
            for (int ni = 0; ni < 8; ++ni) {
                int rb = wn + ni * 8 + gid;
                int base = rb * 32 + tig;
                bf[ni][0] = __float_as_uint(Bf[base + (((kk * 2) ^ (rb & 7)) << 2)]);
                bf[ni][1] = __float_as_uint(Bf[base + (((kk * 2 + 1) ^ (rb & 7)) << 2)]);
            }
#pragma unroll
            for (int mi = 0; mi < 2; ++mi)
#pragma unroll
                for (int ni = 0; ni < 8; ++ni)
                    mma_tf32(acc[mi][ni], af[mi], bf[ni]);
        }
    }
#undef PREFETCH

    // epilogue
#pragma unroll
    for (int mi = 0; mi < 2; ++mi) {
        int r0 = row0 + wm + mi * 16 + gid;
#pragma unroll
        for (int ni = 0; ni < 8; ++ni) {
            int cc = col0 + wn + ni * 8 + tig * 2;
            if (cc < Nn) {
                *(float2*)(C + (size_t)r0 * Nn + cc) =
                    make_float2(acc[mi][ni][0], acc[mi][ni][1]);
                *(float2*)(C + (size_t)(r0 + 8) * Nn + cc) =
                    make_float2(acc[mi][ni][2], acc[mi][ni][3]);
            }
        }
    }
}

// ---------------------------------------------------------------------------
// Causal depthwise conv1d, kernel 4, left pad 3.
// ---------------------------------------------------------------------------
__global__ __launch_bounds__(256) void conv_kernel(
    const float* __restrict__ z, const float* __restrict__ wc,
    const float* __restrict__ bc, float* __restrict__ zc)
{
    int idx = blockIdx.x * 256 + threadIdx.x;
    const int total = BB * LL * TOT;
    if (idx >= total) return;
    int c  = idx % TOT;
    int bl = idx / TOT;
    int l  = bl % LL;

    float acc = bc[c];
#pragma unroll
    for (int jk = 0; jk < CONVK; ++jk) {
        int ls = l - 3 + jk;
        if (ls >= 0)
            acc += wc[jk * TOT + c] * z[(size_t)(bl - 3 + jk) * TOT + c];
    }
    zc[idx] = acc;
}

// ---------------------------------------------------------------------------
// Shared per-thread scan preamble
// ---------------------------------------------------------------------------
struct ScanConst {
    float theta_t, w0, w1, w2, ss, rate;
    bool decay;
};

__device__ __forceinline__ ScanConst scan_consts(
    int k, int j, const float* theta, const float* dslopes,
    const float* aslopes, const float* sscale, const float* dlogits)
{
    ScanConst sc;
    sc.theta_t = theta[k * (HD * MT) + j];
    float dl0 = dlogits[0], dl1 = dlogits[1], dl2 = dlogits[2];
    float mx = fmaxf(dl0, fmaxf(dl1, dl2));
    float e0 = __expf(dl0 - mx), e1 = __expf(dl1 - mx), e2 = __expf(dl2 - mx);
    float dinv = 1.0f / (e0 + e1 + e2);
    sc.w0 = e0 * dinv; sc.w1 = e1 * dinv; sc.w2 = e2 * dinv;
    sc.ss = sscale[k];
    sc.decay = (k < KH - ANCHOR);
    float slope = sc.decay ? dslopes[k] : aslopes[k - (KH - ANCHOR)];
    sc.rate = logf(1.0f + expf(slope));
    return sc;
}

__device__ __forceinline__ void scan_step(
    const ScanConst& sc, float xv, float sv, int l,
    float& accRe, float& accIm, float& accDen)
{
    float parg = fminf(fmaxf(sc.ss * sv, -20.0f), 20.0f);
    float p = __expf(parg);
    float tw = sc.decay ? __expf(-sc.rate * (float)(LL - 1 - l))
                        : __expf(-sc.rate * (float)l);
    float pw = p * tw;
    float phi = xv * sc.theta_t;
    float sbv, cbv;
    __sincosf(phi, &sbv, &cbv);
    float poly = sc.w0 + sc.w1 * xv - sc.w2 * xv * xv;
    float ppw = pw * poly;
    accDen += pw;
    accRe  += ppw * cbv;
    accIm  += ppw * sbv;
}

// ---------------------------------------------------------------------------
// Scan pass 1: per-chunk lane sums. grid = B*K*NC, block = 128.
// ---------------------------------------------------------------------------
__global__ __launch_bounds__(128) void scan_part1(
    const float* __restrict__ zc, const float* __restrict__ theta,
    const float* __restrict__ dslopes, const float* __restrict__ aslopes,
    const float* __restrict__ sscale, const float* __restrict__ dlogits,
    float* __restrict__ part)
{
    __shared__ float sxv[TT * 32];
    __shared__ float ssv[TT];

    const int chunk = blockIdx.x % NC;
    const int bk    = blockIdx.x / NC;
    const int k  = bk % KH;
    const int bb = bk / KH;
    const int tid = threadIdx.x;
    const int j = tid, h = j >> 2;

    const ScanConst sc = scan_consts(k, j, theta, dslopes, aslopes, sscale, dlogits);

    float accRe = 0.0f, accIm = 0.0f, accDen = 0.0f;
    const size_t baserow = (size_t)bb * LL;

    for (int l0 = chunk * CL; l0 < chunk * CL + CL; l0 += TT) {
        __syncthreads();
        {
            int v = tid;
            int t = v >> 5, hh = v & 31;
            sxv[v] = zc[(baserow + l0 + t) * (size_t)TOT + (size_t)k * HD + hh];
            v = tid + 128; t = v >> 5; hh = v & 31;
            sxv[v] = zc[(baserow + l0 + t) * (size_t)TOT + (size_t)k * HD + hh];
            if (tid < TT)
                ssv[tid] = zc[(baserow + l0 + tid) * (size_t)TOT + 2 * DM + k];
        }
        __syncthreads();
#pragma unroll
        for (int t = 0; t < TT; ++t)
            scan_step(sc, sxv[t * 32 + h], ssv[t], l0 + t, accRe, accIm, accDen);
    }

    float* p = part + (size_t)blockIdx.x * 384;
    p[j] = accRe; p[128 + j] = accIm; p[256 + j] = accDen;
}

// ---------------------------------------------------------------------------
// Scan pass 2: exclusive prefix over chunks, in place. grid = B*K, block 128.
// ---------------------------------------------------------------------------
__global__ __launch_bounds__(128) void scan_part2(float* __restrict__ part)
{
    const int bk = blockIdx.x;
    const int j = threadIdx.x;
    float rRe = 0.0f, rIm = 0.0f, rDen = 0.0f;
    for (int c = 0; c < NC; ++c) {
        float* p = part + ((size_t)bk * NC + c) * 384;
        float tRe = p[j], tIm = p[128 + j], tDen = p[256 + j];
        p[j] = rRe; p[128 + j] = rIm; p[256 + j] = rDen;
        rRe += tRe; rIm += tIm; rDen += tDen;
    }
}

// ---------------------------------------------------------------------------
// Scan pass 3: scan + RMS norm + projection + gate. grid = B*K*NC, block 128.
// Output g is tf32-rounded (it feeds the tf32 GEMM2 directly).
// ---------------------------------------------------------------------------
__global__ __launch_bounds__(128) void scan_part3(
    const float* __restrict__ zc, const float* __restrict__ theta,
    const float* __restrict__ dslopes, const float* __restrict__ aslopes,
    const float* __restrict__ sscale, const float* __restrict__ dlogits,
    const float* __restrict__ nscale, const float* __restrict__ W_re,
    const float* __restrict__ W_im, const float* __restrict__ part,
    float* __restrict__ g_out)
{
    extern __shared__ float sm[];
    float* Wre_s = sm;                 // 4096
    float* Wim_s = sm + 4096;          // 4096
    float* sre   = sm + 8192;          // 128*12
    float* sim   = sm + 9728;          // 128*12
    float* ssq   = sm + 11264;         // 8*128
    float* sxv   = sm + 12288;         // 8*32
    float* sgv   = sm + 12544;         // 8*32
    float* ssv   = sm + 12800;         // 8
    float* srsq  = sm + 12808;         // 8
    float* ypart = sm + 12816;         // 4*8*32

    const int chunk = blockIdx.x % NC;
    const int bk    = blockIdx.x / NC;
    const int k  = bk % KH;
    const int bb = bk / KH;
    const int tid = threadIdx.x;
    const int j = tid, h = j >> 2;
    const int lane = tid & 31;
    const int warp = tid >> 5;
    const int c  = warp;
    const int hp = lane;

    const ScanConst sc = scan_consts(k, j, theta, dslopes, aslopes, sscale, dlogits);
    const float ns_re = nscale[j];
    const float ns_im = nscale[HD * MT + j];

    for (int i = tid; i < HD * MT * HD; i += 128) {
        Wre_s[i] = W_re[i];
        Wim_s[i] = W_im[i];
    }

    const float* pfx = part + (size_t)blockIdx.x * 384;
    float accRe = pfx[j], accIm = pfx[128 + j], accDen = pfx[256 + j];
    const size_t baserow = (size_t)bb * LL;

    for (int l0 = chunk * CL; l0 < chunk * CL + CL; l0 += TT) {
        __syncthreads();
        {
            int v = tid;
            int t = v >> 5, hh = v & 31;
            size_t rowA = (baserow + l0 + t) * (size_t)TOT;
            sxv[v] = zc[rowA + (size_t)k * HD + hh];
            sgv[v] = zc[rowA + DM + (size_t)k * HD + hh];
            v = tid + 128; t = v >> 5; hh = v & 31;
            size_t rowB = (baserow + l0 + t) * (size_t)TOT;
            sxv[v] = zc[rowB + (size_t)k * HD + hh];
            sgv[v] = zc[rowB + DM + (size_t)k * HD + hh];
            if (tid < TT)
                ssv[tid] = zc[(baserow + l0 + tid) * (size_t)TOT + 2 * DM + k];
        }
        __syncthreads();

#pragma unroll
        for (int t = 0; t < TT; ++t) {
            scan_step(sc, sxv[t * 32 + h], ssv[t], l0 + t, accRe, accIm, accDen);
            float invd = 1.0f / fmaxf(accDen, 1e-4f);
            float re = accRe * invd;
            float im = accIm * invd;
            sre[j * 12 + t] = re;
            sim[j * 12 + t] = im;
            ssq[t * 128 + j] = re * re + im * im;
        }
        __syncthreads();

        {
            int tt = warp * 2;
#pragma unroll
            for (int q = 0; q < 2; ++q, ++tt) {
                float v = ssq[tt * 128 + lane] + ssq[tt * 128 + lane + 32]
                        + ssq[tt * 128 + lane + 64] + ssq[tt * 128 + lane + 96];
#pragma unroll
                for (int off = 16; off; off >>= 1)
                    v += __shfl_xor_sync(0xffffffffu, v, off);
                if (lane == 0)
                    srsq[tt] = rsqrtf(v * (1.0f / (2.0f * HD * MT)) + 1e-5f);
            }
        }
        __syncthreads();

#pragma unroll
        for (int t = 0; t < TT; ++t) {
            float r = srsq[t];
            sre[j * 12 + t] *= r * ns_re;
            sim[j * 12 + t] *= r * ns_im;
        }
        __syncthreads();

        float acc[TT];
#pragma unroll
        for (int t = 0; t < TT; ++t) acc[t] = 0.0f;
#pragma unroll 8
        for (int jj = 0; jj < 32; ++jj) {
            int jg = c * 32 + jj;
            float wr = Wre_s[jg * 32 + hp];
            float wi = Wim_s[jg * 32 + hp];
            float4 r0 = *(const float4*)(sre + jg * 12);
            float4 r1 = *(const float4*)(sre + jg * 12 + 4);
            float4 i0 = *(const float4*)(sim + jg * 12);
            float4 i1 = *(const float4*)(sim + jg * 12 + 4);
            acc[0] += r0.x * wr + i0.x * wi;
            acc[1] += r0.y * wr + i0.y * wi;
            acc[2] += r0.z * wr + i0.z * wi;
            acc[3] += r0.w * wr + i0.w * wi;
            acc[4] += r1.x * wr + i1.x * wi;
            acc[5] += r1.y * wr + i1.y * wi;
            acc[6] += r1.z * wr + i1.z * wi;
            acc[7] += r1.w * wr + i1.w * wi;
        }
#pragma unroll
        for (int t = 0; t < TT; ++t)
            ypart[(c * TT + t) * 32 + hp] = acc[t];
        __syncthreads();

        for (int v = tid; v < TT * 32; v += 128) {
            int t = v >> 5, hh = v & 31;
            float y = ypart[t * 32 + hh] + ypart[(TT + t) * 32 + hh]
                    + ypart[(2 * TT + t) * 32 + hh] + ypart[(3 * TT + t) * 32 + hh];
            float gz = sgv[t * 32 + hh];
            float gate = gz / (1.0f + __expf(-gz));
            g_out[(baserow + l0 + t) * (size_t)DM + (size_t)k * HD + hh] =
                f2tf_f(y * gate);
        }
    }
}

// ---------------------------------------------------------------------------
extern "C" void kernel_launch(void* const* d_in, const int* in_sizes, int n_in,
                              void* d_out, int out_size)
{
    const float* x       = (const float*)d_in[0];
    const float* W_in    = (const float*)d_in[1];
    const float* w_conv  = (const float*)d_in[2];
    const float* b_conv  = (const float*)d_in[3];
    const float* theta   = (const float*)d_in[4];
    const float* dslopes = (const float*)d_in[5];
    const float* aslopes = (const float*)d_in[6];
    const float* sscale  = (const float*)d_in[7];
    const float* dlogits = (const float*)d_in[8];
    const float* nscale  = (const float*)d_in[9];
    const float* W_re    = (const float*)d_in[10];
    const float* W_im    = (const float*)d_in[11];
    const float* W_out   = (const float*)d_in[12];
    float* out = (float*)d_out;

    float *pz, *pzc, *pg, *px32, *pbt1, *pbt2, *ppart;
    cudaGetSymbolAddress((void**)&pz,    g_z);
    cudaGetSymbolAddress((void**)&pzc,   g_zc);
    cudaGetSymbolAddress((void**)&pg,    g_g);
    cudaGetSymbolAddress((void**)&px32,  g_x32);
    cudaGetSymbolAddress((void**)&pbt1,  g_bt1);
    cudaGetSymbolAddress((void**)&pbt2,  g_bt2);
    cudaGetSymbolAddress((void**)&ppart, g_part);

    static bool attr_set = false;
    if (!attr_set) {
        cudaFuncSetAttribute(gemm_cp,
                             cudaFuncAttributeMaxDynamicSharedMemorySize, GEMM_SMEM);
        cudaFuncSetAttribute(scan_part3,
                             cudaFuncAttributeMaxDynamicSharedMemorySize, 56 * 1024);
        attr_set = true;
    }

    // 0a) transpose + round weights to K-major tf32
    transpose_k<<<dim3((TOT + 31) / 32, DM / 32), 256>>>(W_in, pbt1, DM, TOT);
    transpose_k<<<dim3(DM / 32, DM / 32), 256>>>(W_out, pbt2, DM, DM);
    // 0b) round x to tf32
    {
        int n4 = BB * LL * DM / 4;
        round_tf32_k<<<(n4 + 255) / 256, 256>>>((const float4*)x, (float4*)px32, n4);
    }

    // 1) z = x @ W_in   (8192 x 2080, K=1024)  — TF32 mma.sync, cp.async pipeline
    {
        dim3 grid((TOT + 127) / 128, (BB * LL) / 128);
        gemm_cp<<<grid, 256, GEMM_SMEM>>>(px32, pbt1, pz, BB * LL, TOT, DM);
    }
    // 2) causal depthwise conv
    {
        int total = BB * LL * TOT;
        conv_kernel<<<(total + 255) / 256, 256>>>(pz, w_conv, b_conv, pzc);
    }
    // 3) chunked parallel scan (3 passes)
    scan_part1<<<BB * KH * NC, 128>>>(pzc, theta, dslopes, aslopes,
                                      sscale, dlogits, ppart);
    scan_part2<<<BB * KH, 128>>>(ppart);
    scan_part3<<<BB * KH * NC, 128, 55360>>>(pzc, theta, dslopes, aslopes,
                                             sscale, dlogits, nscale,
                                             W_re, W_im, ppart, pg);
    // 4) out = g @ W_out  (8192 x 1024, K=1024) — TF32 mma.sync, cp.async pipeline
    {
        dim3 grid(DM / 128, (BB * LL) / 128);
        gemm_cp<<<grid, 256, GEMM_SMEM>>>(pg, pbt2, out, BB * LL, DM, DM);
    }
}

// round 7
// speedup vs baseline: 3.5886x; 1.1822x over previous
#include <cuda_runtime.h>
#include <cuda_bf16.h>
#include <cstdint>

// Problem constants
#define BB   4
#define LL   2048
#define DM   1024
#define KH   32        // heads
#define HD   32        // head dim
#define MT   4         // m_theta
#define TOT  2080      // 2*DM + KH
#define CONVK 4
#define ANCHOR 4
#define TT   8         // scan tile (time steps per tile)
#define NC   32        // scan chunks
#define CL   (LL / NC) // 64 steps per chunk
#define PM   (BB * LL * KH)   // 262144 projection rows

// Scratch (static device globals — no runtime allocation allowed)
__device__ float g_z   [BB * LL * TOT];   // x @ W_in
__device__ float g_zc  [BB * LL * TOT];   // after causal depthwise conv
__device__ float g_g   [BB * LL * DM];    // gated y (input to final GEMM), tf32-rounded
__device__ float g_x32 [BB * LL * DM];    // x rounded to tf32
__device__ float g_bt1 [TOT * DM];        // W_in^T  (2080 x 1024), K-major, tf32-rounded
__device__ float g_bt2 [DM * DM];         // W_out^T (1024 x 1024), tf32-rounded
__device__ float g_btp [32 * 256];        // [W_re;W_im]^T (32 x 256), tf32-rounded
__device__ float g_pa  [PM * 256];        // normalized [re|im] rows for projection
__device__ float g_part[BB * KH * NC * 3 * 128];  // chunk partials / prefixes

// ---------------------------------------------------------------------------
// TF32 helpers
// ---------------------------------------------------------------------------
__device__ __forceinline__ uint32_t f2tf(float f) {
    uint32_t u;
    asm("cvt.rna.tf32.f32 %0, %1;" : "=r"(u) : "f"(f));
    return u;
}
__device__ __forceinline__ float f2tf_f(float f) {
    return __uint_as_float(f2tf(f));
}

__device__ __forceinline__ void mma_tf32(float* c4, const uint32_t* a4,
                                         const uint32_t* b2) {
    asm volatile(
        "mma.sync.aligned.m16n8k8.row.col.f32.tf32.tf32.f32 "
        "{%0,%1,%2,%3}, {%4,%5,%6,%7}, {%8,%9}, {%0,%1,%2,%3};"
        : "+f"(c4[0]), "+f"(c4[1]), "+f"(c4[2]), "+f"(c4[3])
        : "r"(a4[0]), "r"(a4[1]), "r"(a4[2]), "r"(a4[3]),
          "r"(b2[0]), "r"(b2[1]));
}

__device__ __forceinline__ uint32_t smem_u32(const void* p) {
    uint32_t a;
    asm("{ .reg .u64 t; cvta.to.shared.u64 t, %1; cvt.u32.u64 %0, t; }"
        : "=r"(a) : "l"(p));
    return a;
}
__device__ __forceinline__ void cpa16(uint32_t d, const void* s, int sz) {
    asm volatile("cp.async.cg.shared.global [%0], [%1], 16, %2;"
                 :: "r"(d), "l"(s), "r"(sz));
}
#define CP_COMMIT() asm volatile("cp.async.commit_group;" ::: "memory")
#define CP_WAIT1()  asm volatile("cp.async.wait_group 1;" ::: "memory")

// ---------------------------------------------------------------------------
// Round fp32 array to tf32 (RNA), vectorized. n4 = element count / 4.
// ---------------------------------------------------------------------------
__global__ __launch_bounds__(256) void round_tf32_k(
    const float4* __restrict__ src, float4* __restrict__ dst, int n4)
{
    int i = blockIdx.x * 256 + threadIdx.x;
    if (i < n4) {
        float4 v = src[i];
        v.x = f2tf_f(v.x); v.y = f2tf_f(v.y);
        v.z = f2tf_f(v.z); v.w = f2tf_f(v.w);
        dst[i] = v;
    }
}

// ---------------------------------------------------------------------------
// Tiled transpose with tf32 rounding: D[C][R] = round_tf32(S[R][C]^T)
// ---------------------------------------------------------------------------
__global__ __launch_bounds__(256) void transpose_k(
    const float* __restrict__ S, float* __restrict__ D, int R, int C)
{
    __shared__ float t[32][33];
    int c0 = blockIdx.x * 32, r0 = blockIdx.y * 32;
    int x = threadIdx.x & 31, y = threadIdx.x >> 5;   // 32 x 8
#pragma unroll
    for (int i = 0; i < 32; i += 8) {
        int r = r0 + y + i, c = c0 + x;
        t[y + i][x] = (r < R && c < C) ? S[(size_t)r * C + c] : 0.0f;
    }
    __syncthreads();
#pragma unroll
    for (int i = 0; i < 32; i += 8) {
        int r = c0 + y + i, c = r0 + x;
        if (r < C && c < R) D[(size_t)r * R + c] = f2tf_f(t[x][y + i]);
    }
}

// ---------------------------------------------------------------------------
// Projection weight prep: Bt(32 x 256), Bt[n][kk] = [W_re;W_im][kk][n]
// ---------------------------------------------------------------------------
__global__ __launch_bounds__(256) void proj_wprep(
    const float* __restrict__ Wre, const float* __restrict__ Wim,
    float* __restrict__ Bt)
{
    int i = blockIdx.x * 256 + threadIdx.x;
    if (i < 32 * 256) {
        int n = i >> 8, kk = i & 255;
        float v = (kk < 128) ? Wre[kk * 32 + n] : Wim[(kk - 128) * 32 + n];
        Bt[i] = f2tf_f(v);
    }
}

// ---------------------------------------------------------------------------
// TF32 tensor-core GEMM, cp.async 3-stage pipeline (unchanged from R5):
//   C(M,Nn) = A(M,Kd) * Bt(Nn,Kd)^T; A and Bt pre-rounded to tf32.
// ---------------------------------------------------------------------------
#define GKC 32
#define STAGE_BYTES 32768
#define GEMM_SMEM  (3 * STAGE_BYTES)

__global__ __launch_bounds__(256, 2) void gemm_cp(
    const float* __restrict__ A, const float* __restrict__ Bt,
    float* __restrict__ C, int M, int Nn, int Kd)
{
    extern __shared__ float smem[];
    const uint32_t sbase = smem_u32(smem);
    const int tid = threadIdx.x;
    const int wid = tid >> 5, lane = tid & 31;
    const int gid = lane >> 2, tig = lane & 3;
    const int wm = (wid >> 1) * 32;
    const int wn = (wid & 1) * 64;
    const int row0 = blockIdx.y * 128;
    const int col0 = blockIdx.x * 128;
    const int NCH = Kd / GKC;

    float acc[2][8][4];
#pragma unroll
    for (int mi = 0; mi < 2; ++mi)
#pragma unroll
        for (int ni = 0; ni < 8; ++ni)
#pragma unroll
            for (int q = 0; q < 4; ++q) acc[mi][ni][q] = 0.0f;

    int prow[4], pseg[4];
    uint32_t poff[4];
#pragma unroll
    for (int i = 0; i < 4; ++i) {
        int idx = i * 256 + tid;
        prow[i] = idx >> 3;
        pseg[i] = idx & 7;
        poff[i] = (uint32_t)(prow[i] * 128 + ((pseg[i] ^ (prow[i] & 7)) << 4));
    }

#define PREFETCH(pc) do {                                                     \
    if ((pc) < NCH) {                                                         \
        int k0 = (pc) * GKC;                                                  \
        uint32_t stb = sbase + ((pc) % 3) * STAGE_BYTES;                      \
        _Pragma("unroll")                                                     \
        for (int i = 0; i < 4; ++i) {                                         \
            cpa16(stb + poff[i],                                              \
                  A + (size_t)(row0 + prow[i]) * Kd + k0 + pseg[i] * 4, 16);  \
            int nr = col0 + prow[i];                                          \
            int ok = (nr < Nn);                                               \
            cpa16(stb + 16384 + poff[i],                                      \
                  Bt + (size_t)(ok ? nr : 0) * Kd + k0 + pseg[i] * 4,         \
                  ok ? 16 : 0);                                               \
        }                                                                     \
    }                                                                         \
    CP_COMMIT();                                                              \
} while (0)

    PREFETCH(0);
    PREFETCH(1);

    for (int c = 0; c < NCH; ++c) {
        CP_WAIT1();
        __syncthreads();
        PREFETCH(c + 2);

        const float* Af = smem + (c % 3) * 8192;
        const float* Bf = Af + 4096;

#pragma unroll
        for (int kk = 0; kk < 4; ++kk) {
            uint32_t af[2][4];
#pragma unroll
            for (int mi = 0; mi < 2; ++mi) {
                int ra = wm + mi * 16 + gid;
                int s0 = ((kk * 2) ^ (ra & 7)) << 2;
                int s1 = ((kk * 2 + 1) ^ (ra & 7)) << 2;
                int base = ra * 32 + tig;
                af[mi][0] = __float_as_uint(Af[base + s0]);
                af[mi][1] = __float_as_uint(Af[base + s0 + 256]);
                af[mi][2] = __float_as_uint(Af[base + s1]);
                af[mi][3] = __float_as_uint(Af[base + s1 + 256]);
            }
            uint32_t bf[8][2];
#pragma unroll
            for (int ni = 0; ni < 8; ++ni) {
                int rb = wn + ni * 8 + gid;
                int base = rb * 32 + tig;
                bf[ni][0] = __float_as_uint(Bf[base + (((kk * 2) ^ (rb & 7)) << 2)]);
                bf[ni][1] = __float_as_uint(Bf[base + (((kk * 2 + 1) ^ (rb & 7)) << 2)]);
            }
#pragma unroll
            for (int mi = 0; mi < 2; ++mi)
#pragma unroll
                for (int ni = 0; ni < 8; ++ni)
                    mma_tf32(acc[mi][ni], af[mi], bf[ni]);
        }
    }
#undef PREFETCH

#pragma unroll
    for (int mi = 0; mi < 2; ++mi) {
        int r0 = row0 + wm + mi * 16 + gid;
#pragma unroll
        for (int ni = 0; ni < 8; ++ni) {
            int cc = col0 + wn + ni * 8 + tig * 2;
            if (cc < Nn) {
                *(float2*)(C + (size_t)r0 * Nn + cc) =
                    make_float2(acc[mi][ni][0], acc[mi][ni][1]);
                *(float2*)(C + (size_t)(r0 + 8) * Nn + cc) =
                    make_float2(acc[mi][ni][2], acc[mi][ni][3]);
            }
        }
    }
}

// ---------------------------------------------------------------------------
// Projection GEMM with gate epilogue:
//   C(PM x 32) = A(PM x 256) @ Bt(32 x 256)^T;   C[r][c] *= silu(gate(r,c))
//   C row-major == g(B,L,D) exactly. Output tf32-rounded.
// 256-row tile, 256 threads (8 warps stacked in M), warp tile 32x32.
// ---------------------------------------------------------------------------
#define PKC 32
#define PSTAGE 36864             // A 32768 + B 4096
#define PROJ_SMEM (3 * PSTAGE)

__global__ __launch_bounds__(256, 2) void proj_gemm(
    const float* __restrict__ A, const float* __restrict__ Bt,
    const float* __restrict__ zc, float* __restrict__ C)
{
    extern __shared__ float smem[];
    const uint32_t sbase = smem_u32(smem);
    const int tid = threadIdx.x;
    const int wid = tid >> 5, lane = tid & 31;
    const int gid = lane >> 2, tig = lane & 3;
    const int row0 = blockIdx.x * 256;

    float acc[2][4][4];
#pragma unroll
    for (int mi = 0; mi < 2; ++mi)
#pragma unroll
        for (int ni = 0; ni < 4; ++ni)
#pragma unroll
            for (int q = 0; q < 4; ++q) acc[mi][ni][q] = 0.0f;

    // A copy coords: 8 x 16B per thread (256 rows x 8 segs)
    int arow[8], aseg[8];
    uint32_t aoff[8];
#pragma unroll
    for (int i = 0; i < 8; ++i) {
        int idx = i * 256 + tid;
        arow[i] = idx >> 3;
        aseg[i] = idx & 7;
        aoff[i] = (uint32_t)(arow[i] * 128 + ((aseg[i] ^ (arow[i] & 7)) << 4));
    }
    // B copy coords: 1 x 16B per thread (32 rows x 8 segs)
    const int brow = tid >> 3, bseg = tid & 7;
    const uint32_t boff = (uint32_t)(brow * 128 + ((bseg ^ (brow & 7)) << 4));

#define PPRE(pc) do {                                                         \
    if ((pc) < 8) {                                                           \
        int k0 = (pc) * PKC;                                                  \
        uint32_t stb = sbase + ((pc) % 3) * PSTAGE;                           \
        _Pragma("unroll")                                                     \
        for (int i = 0; i < 8; ++i)                                           \
            cpa16(stb + aoff[i],                                              \
                  A + (size_t)(row0 + arow[i]) * 256 + k0 + aseg[i] * 4, 16); \
        cpa16(stb + 32768 + boff, Bt + brow * 256 + k0 + bseg * 4, 16);       \
    }                                                                         \
    CP_COMMIT();                                                              \
} while (0)

    PPRE(0);
    PPRE(1);

    for (int c = 0; c < 8; ++c) {
        CP_WAIT1();
        __syncthreads();
        PPRE(c + 2);

        const float* Af = smem + (c % 3) * 9216;
        const float* Bf = Af + 8192;

#pragma unroll
        for (int kk = 0; kk < 4; ++kk) {
            uint32_t af[2][4];
#pragma unroll
            for (int mi = 0; mi < 2; ++mi) {
                int ra = wid * 32 + mi * 16 + gid;
                int s0 = ((kk * 2) ^ (ra & 7)) << 2;
                int s1 = ((kk * 2 + 1) ^ (ra & 7)) << 2;
                int base = ra * 32 + tig;
                af[mi][0] = __float_as_uint(Af[base + s0]);
                af[mi][1] = __float_as_uint(Af[base + s0 + 256]);
                af[mi][2] = __float_as_uint(Af[base + s1]);
                af[mi][3] = __float_as_uint(Af[base + s1 + 256]);
            }
            uint32_t bf[4][2];
#pragma unroll
            for (int ni = 0; ni < 4; ++ni) {
                int rb = ni * 8 + gid;
                int base = rb * 32 + tig;
                bf[ni][0] = __float_as_uint(Bf[base + (((kk * 2) ^ (rb & 7)) << 2)]);
                bf[ni][1] = __float_as_uint(Bf[base + (((kk * 2 + 1) ^ (rb & 7)) << 2)]);
            }
#pragma unroll
            for (int mi = 0; mi < 2; ++mi)
#pragma unroll
                for (int ni = 0; ni < 4; ++ni)
                    mma_tf32(acc[mi][ni], af[mi], bf[ni]);
        }
    }
#undef PPRE

    // epilogue: SiLU gate + tf32 round + store (C row-major == g(B,L,D))
#pragma unroll
    for (int mi = 0; mi < 2; ++mi) {
#pragma unroll
        for (int rg = 0; rg < 2; ++rg) {
            int r = row0 + wid * 32 + mi * 16 + gid + rg * 8;
            int bl = r >> 5, k = r & 31;
            size_t gbase = (size_t)bl * TOT + DM + k * HD;
#pragma unroll
            for (int ni = 0; ni < 4; ++ni) {
                int cc = ni * 8 + tig * 2;
                float gz0 = zc[gbase + cc];
                float gz1 = zc[gbase + cc + 1];
                float s0 = gz0 / (1.0f + __expf(-gz0));
                float s1 = gz1 / (1.0f + __expf(-gz1));
                *(float2*)(C + (size_t)r * 32 + cc) = make_float2(
                    f2tf_f(acc[mi][ni][rg * 2 + 0] * s0),
                    f2tf_f(acc[mi][ni][rg * 2 + 1] * s1));
            }
        }
    }
}

// ---------------------------------------------------------------------------
// Causal depthwise conv1d, kernel 4, left pad 3.
// ---------------------------------------------------------------------------
__global__ __launch_bounds__(256) void conv_kernel(
    const float* __restrict__ z, const float* __restrict__ wc,
    const float* __restrict__ bc, float* __restrict__ zc)
{
    int idx = blockIdx.x * 256 + threadIdx.x;
    const int total = BB * LL * TOT;
    if (idx >= total) return;
    int c  = idx % TOT;
    int bl = idx / TOT;
    int l  = bl % LL;

    float acc = bc[c];
#pragma unroll
    for (int jk = 0; jk < CONVK; ++jk) {
        int ls = l - 3 + jk;
        if (ls >= 0)
            acc += wc[jk * TOT + c] * z[(size_t)(bl - 3 + jk) * TOT + c];
    }
    zc[idx] = acc;
}

// ---------------------------------------------------------------------------
// Shared per-thread scan preamble
// ---------------------------------------------------------------------------
struct ScanConst {
    float theta_t, w0, w1, w2, ss, rate;
    bool decay;
};

__device__ __forceinline__ ScanConst scan_consts(
    int k, int j, const float* theta, const float* dslopes,
    const float* aslopes, const float* sscale, const float* dlogits)
{
    ScanConst sc;
    sc.theta_t = theta[k * (HD * MT) + j];
    float dl0 = dlogits[0], dl1 = dlogits[1], dl2 = dlogits[2];
    float mx = fmaxf(dl0, fmaxf(dl1, dl2));
    float e0 = __expf(dl0 - mx), e1 = __expf(dl1 - mx), e2 = __expf(dl2 - mx);
    float dinv = 1.0f / (e0 + e1 + e2);
    sc.w0 = e0 * dinv; sc.w1 = e1 * dinv; sc.w2 = e2 * dinv;
    sc.ss = sscale[k];
    sc.decay = (k < KH - ANCHOR);
    float slope = sc.decay ? dslopes[k] : aslopes[k - (KH - ANCHOR)];
    sc.rate = logf(1.0f + expf(slope));
    return sc;
}

__device__ __forceinline__ void scan_step(
    const ScanConst& sc, float xv, float sv, int l,
    float& accRe, float& accIm, float& accDen)
{
    float parg = fminf(fmaxf(sc.ss * sv, -20.0f), 20.0f);
    float p = __expf(parg);
    float tw = sc.decay ? __expf(-sc.rate * (float)(LL - 1 - l))
                        : __expf(-sc.rate * (float)l);
    float pw = p * tw;
    float phi = xv * sc.theta_t;
    float sbv, cbv;
    __sincosf(phi, &sbv, &cbv);
    float poly = sc.w0 + sc.w1 * xv - sc.w2 * xv * xv;
    float ppw = pw * poly;
    accDen += pw;
    accRe  += ppw * cbv;
    accIm  += ppw * sbv;
}

// ---------------------------------------------------------------------------
// Scan pass 1: per-chunk lane sums. grid = B*K*NC, block = 128.
// ---------------------------------------------------------------------------
__global__ __launch_bounds__(128) void scan_part1(
    const float* __restrict__ zc, const float* __restrict__ theta,
    const float* __restrict__ dslopes, const float* __restrict__ aslopes,
    const float* __restrict__ sscale, const float* __restrict__ dlogits,
    float* __restrict__ part)
{
    __shared__ float sxv[TT * 32];
    __shared__ float ssv[TT];

    const int chunk = blockIdx.x % NC;
    const int bk    = blockIdx.x / NC;
    const int k  = bk % KH;
    const int bb = bk / KH;
    const int tid = threadIdx.x;
    const int j = tid, h = j >> 2;

    const ScanConst sc = scan_consts(k, j, theta, dslopes, aslopes, sscale, dlogits);

    float accRe = 0.0f, accIm = 0.0f, accDen = 0.0f;
    const size_t baserow = (size_t)bb * LL;

    for (int l0 = chunk * CL; l0 < chunk * CL + CL; l0 += TT) {
        __syncthreads();
        {
            int v = tid;
            int t = v >> 5, hh = v & 31;
            sxv[v] = zc[(baserow + l0 + t) * (size_t)TOT + (size_t)k * HD + hh];
            v = tid + 128; t = v >> 5; hh = v & 31;
            sxv[v] = zc[(baserow + l0 + t) * (size_t)TOT + (size_t)k * HD + hh];
            if (tid < TT)
                ssv[tid] = zc[(baserow + l0 + tid) * (size_t)TOT + 2 * DM + k];
        }
        __syncthreads();
#pragma unroll
        for (int t = 0; t < TT; ++t)
            scan_step(sc, sxv[t * 32 + h], ssv[t], l0 + t, accRe, accIm, accDen);
    }

    float* p = part + (size_t)blockIdx.x * 384;
    p[j] = accRe; p[128 + j] = accIm; p[256 + j] = accDen;
}

// ---------------------------------------------------------------------------
// Scan pass 2: exclusive prefix over chunks, in place. grid = B*K, block 128.
// ---------------------------------------------------------------------------
__global__ __launch_bounds__(128) void scan_part2(float* __restrict__ part)
{
    const int bk = blockIdx.x;
    const int j = threadIdx.x;
    float rRe = 0.0f, rIm = 0.0f, rDen = 0.0f;
    for (int c = 0; c < NC; ++c) {
        float* p = part + ((size_t)bk * NC + c) * 384;
        float tRe = p[j], tIm = p[128 + j], tDen = p[256 + j];
        p[j] = rRe; p[128 + j] = rIm; p[256 + j] = rDen;
        rRe += tRe; rIm += tIm; rDen += tDen;
    }
}

// ---------------------------------------------------------------------------
// Scan pass 3 (lite): scan + joint RMS norm; writes normalized [re|im] rows
// to gA (PM x 256) for the projection GEMM. grid = B*K*NC, block = 128.
// ---------------------------------------------------------------------------
__global__ __launch_bounds__(128) void scan_part3(
    const float* __restrict__ zc, const float* __restrict__ theta,
    const float* __restrict__ dslopes, const float* __restrict__ aslopes,
    const float* __restrict__ sscale, const float* __restrict__ dlogits,
    const float* __restrict__ nscale, const float* __restrict__ part,
    float* __restrict__ gA)
{
    __shared__ float sxv[TT * 32];
    __shared__ float ssv[TT];
    __shared__ float ssq[TT * 128];
    __shared__ float srsq[TT];

    const int chunk = blockIdx.x % NC;
    const int bk    = blockIdx.x / NC;
    const int k  = bk % KH;
    const int bb = bk / KH;
    const int tid = threadIdx.x;
    const int j = tid, h = j >> 2;
    const int lane = tid & 31;
    const int warp = tid >> 5;

    const ScanConst sc = scan_consts(k, j, theta, dslopes, aslopes, sscale, dlogits);
    const float ns_re = nscale[j];
    const float ns_im = nscale[HD * MT + j];

    const float* pfx = part + (size_t)blockIdx.x * 384;
    float accRe = pfx[j], accIm = pfx[128 + j], accDen = pfx[256 + j];
    const size_t baserow = (size_t)bb * LL;

    for (int l0 = chunk * CL; l0 < chunk * CL + CL; l0 += TT) {
        __syncthreads();
        {
            int v = tid;
            int t = v >> 5, hh = v & 31;
            sxv[v] = zc[(baserow + l0 + t) * (size_t)TOT + (size_t)k * HD + hh];
            v = tid + 128; t = v >> 5; hh = v & 31;
            sxv[v] = zc[(baserow + l0 + t) * (size_t)TOT + (size_t)k * HD + hh];
            if (tid < TT)
                ssv[tid] = zc[(baserow + l0 + tid) * (size_t)TOT + 2 * DM + k];
        }
        __syncthreads();

        float re[TT], im[TT];
#pragma unroll
        for (int t = 0; t < TT; ++t) {
            scan_step(sc, sxv[t * 32 + h], ssv[t], l0 + t, accRe, accIm, accDen);
            float invd = 1.0f / fmaxf(accDen, 1e-4f);
            re[t] = accRe * invd;
            im[t] = accIm * invd;
            ssq[t * 128 + j] = re[t] * re[t] + im[t] * im[t];
        }
        __syncthreads();

        {
            int tt = warp * 2;
#pragma unroll
            for (int q = 0; q < 2; ++q, ++tt) {
                float v = ssq[tt * 128 + lane] + ssq[tt * 128 + lane + 32]
                        + ssq[tt * 128 + lane + 64] + ssq[tt * 128 + lane + 96];
#pragma unroll
                for (int off = 16; off; off >>= 1)
                    v += __shfl_xor_sync(0xffffffffu, v, off);
                if (lane == 0)
                    srsq[tt] = rsqrtf(v * (1.0f / (2.0f * HD * MT)) + 1e-5f);
            }
        }
        __syncthreads();

#pragma unroll
        for (int t = 0; t < TT; ++t) {
            float r = srsq[t];
            size_t row = ((baserow + l0 + t) * (size_t)KH + k) * 256;
            gA[row + j]       = f2tf_f(re[t] * r * ns_re);
            gA[row + 128 + j] = f2tf_f(im[t] * r * ns_im);
        }
    }
}

// ---------------------------------------------------------------------------
extern "C" void kernel_launch(void* const* d_in, const int* in_sizes, int n_in,
                              void* d_out, int out_size)
{
    const float* x       = (const float*)d_in[0];
    const float* W_in    = (const float*)d_in[1];
    const float* w_conv  = (const float*)d_in[2];
    const float* b_conv  = (const float*)d_in[3];
    const float* theta   = (const float*)d_in[4];
    const float* dslopes = (const float*)d_in[5];
    const float* aslopes = (const float*)d_in[6];
    const float* sscale  = (const float*)d_in[7];
    const float* dlogits = (const float*)d_in[8];
    const float* nscale  = (const float*)d_in[9];
    const float* W_re    = (const float*)d_in[10];
    const float* W_im    = (const float*)d_in[11];
    const float* W_out   = (const float*)d_in[12];
    float* out = (float*)d_out;

    float *pz, *pzc, *pg, *px32, *pbt1, *pbt2, *pbtp, *ppa, *ppart;
    cudaGetSymbolAddress((void**)&pz,    g_z);
    cudaGetSymbolAddress((void**)&pzc,   g_zc);
    cudaGetSymbolAddress((void**)&pg,    g_g);
    cudaGetSymbolAddress((void**)&px32,  g_x32);
    cudaGetSymbolAddress((void**)&pbt1,  g_bt1);
    cudaGetSymbolAddress((void**)&pbt2,  g_bt2);
    cudaGetSymbolAddress((void**)&pbtp,  g_btp);
    cudaGetSymbolAddress((void**)&ppa,   g_pa);
    cudaGetSymbolAddress((void**)&ppart, g_part);

    static bool attr_set = false;
    if (!attr_set) {
        cudaFuncSetAttribute(gemm_cp,
                             cudaFuncAttributeMaxDynamicSharedMemorySize, GEMM_SMEM);
        cudaFuncSetAttribute(proj_gemm,
                             cudaFuncAttributeMaxDynamicSharedMemorySize, PROJ_SMEM);
        attr_set = true;
    }

    // 0) weight prep + x rounding
    transpose_k<<<dim3((TOT + 31) / 32, DM / 32), 256>>>(W_in, pbt1, DM, TOT);
    transpose_k<<<dim3(DM / 32, DM / 32), 256>>>(W_out, pbt2, DM, DM);
    proj_wprep<<<32, 256>>>(W_re, W_im, pbtp);
    {
        int n4 = BB * LL * DM / 4;
        round_tf32_k<<<(n4 + 255) / 256, 256>>>((const float4*)x, (float4*)px32, n4);
    }

    // 1) z = x @ W_in   — TF32 mma.sync, cp.async pipeline
    {
        dim3 grid((TOT + 127) / 128, (BB * LL) / 128);
        gemm_cp<<<grid, 256, GEMM_SMEM>>>(px32, pbt1, pz, BB * LL, TOT, DM);
    }
    // 2) causal depthwise conv
    {
        int total = BB * LL * TOT;
        conv_kernel<<<(total + 255) / 256, 256>>>(pz, w_conv, b_conv, pzc);
    }
    // 3) chunked parallel scan (3 passes; part3 emits normalized [re|im])
    scan_part1<<<BB * KH * NC, 128>>>(pzc, theta, dslopes, aslopes,
                                      sscale, dlogits, ppart);
    scan_part2<<<BB * KH, 128>>>(ppart);
    scan_part3<<<BB * KH * NC, 128>>>(pzc, theta, dslopes, aslopes,
                                      sscale, dlogits, nscale, ppart, ppa);
    // 3b) projection GEMM + SiLU gate epilogue -> g
    proj_gemm<<<PM / 256, 256, PROJ_SMEM>>>(ppa, pbtp, pzc, pg);

    // 4) out = g @ W_out — TF32 mma.sync, cp.async pipeline
    {
        dim3 grid(DM / 128, (BB * LL) / 128);
        gemm_cp<<<grid, 256, GEMM_SMEM>>>(pg, pbt2, out, BB * LL, DM, DM);
    }
}

// round 8
// speedup vs baseline: 3.7638x; 1.0488x over previous
#include <cuda_runtime.h>
#include <cuda_bf16.h>
#include <cstdint>

// Problem constants
#define BB   4
#define LL   2048
#define DM   1024
#define KH   32        // heads
#define HD   32        // head dim
#define MT   4         // m_theta
#define TOT  2080      // 2*DM + KH
#define CONVK 4
#define ANCHOR 4
#define TT   8         // scan tile (time steps per tile)
#define NC   32        // scan chunks
#define CL   (LL / NC) // 64 steps per chunk

// Scratch (static device globals — no runtime allocation allowed)
__device__ float g_z   [BB * LL * TOT];   // x @ W_in
__device__ float g_zc  [BB * LL * TOT];   // after causal depthwise conv
__device__ float g_g   [BB * LL * DM];    // gated y (input to final GEMM), tf32-rounded
__device__ float g_x32 [BB * LL * DM];    // x rounded to tf32
__device__ float g_bt1 [TOT * DM];        // W_in^T  (2080 x 1024), K-major, tf32-rounded
__device__ float g_bt2 [DM * DM];         // W_out^T (1024 x 1024), tf32-rounded
__device__ float g_btp [32 * 256];        // [W_re;W_im]^T (32 x 256), tf32-rounded
__device__ float g_part[BB * KH * NC * 3 * 128];  // chunk partials / prefixes

// ---------------------------------------------------------------------------
// TF32 helpers
// ---------------------------------------------------------------------------
__device__ __forceinline__ uint32_t f2tf(float f) {
    uint32_t u;
    asm("cvt.rna.tf32.f32 %0, %1;" : "=r"(u) : "f"(f));
    return u;
}
__device__ __forceinline__ float f2tf_f(float f) {
    return __uint_as_float(f2tf(f));
}

__device__ __forceinline__ void mma_tf32(float* c4, const uint32_t* a4,
                                         const uint32_t* b2) {
    asm volatile(
        "mma.sync.aligned.m16n8k8.row.col.f32.tf32.tf32.f32 "
        "{%0,%1,%2,%3}, {%4,%5,%6,%7}, {%8,%9}, {%0,%1,%2,%3};"
        : "+f"(c4[0]), "+f"(c4[1]), "+f"(c4[2]), "+f"(c4[3])
        : "r"(a4[0]), "r"(a4[1]), "r"(a4[2]), "r"(a4[3]),
          "r"(b2[0]), "r"(b2[1]));
}

__device__ __forceinline__ uint32_t smem_u32(const void* p) {
    uint32_t a;
    asm("{ .reg .u64 t; cvta.to.shared.u64 t, %1; cvt.u32.u64 %0, t; }"
        : "=r"(a) : "l"(p));
    return a;
}
__device__ __forceinline__ void cpa16(uint32_t d, const void* s, int sz) {
    asm volatile("cp.async.cg.shared.global [%0], [%1], 16, %2;"
                 :: "r"(d), "l"(s), "r"(sz));
}
#define CP_COMMIT() asm volatile("cp.async.commit_group;" ::: "memory")
#define CP_WAIT1()  asm volatile("cp.async.wait_group 1;" ::: "memory")

// ---------------------------------------------------------------------------
// Round fp32 array to tf32 (RNA), vectorized.
// ---------------------------------------------------------------------------
__global__ __launch_bounds__(256) void round_tf32_k(
    const float4* __restrict__ src, float4* __restrict__ dst, int n4)
{
    int i = blockIdx.x * 256 + threadIdx.x;
    if (i < n4) {
        float4 v = src[i];
        v.x = f2tf_f(v.x); v.y = f2tf_f(v.y);
        v.z = f2tf_f(v.z); v.w = f2tf_f(v.w);
        dst[i] = v;
    }
}

// ---------------------------------------------------------------------------
// Tiled transpose with tf32 rounding: D[C][R] = round_tf32(S[R][C]^T)
// ---------------------------------------------------------------------------
__global__ __launch_bounds__(256) void transpose_k(
    const float* __restrict__ S, float* __restrict__ D, int R, int C)
{
    __shared__ float t[32][33];
    int c0 = blockIdx.x * 32, r0 = blockIdx.y * 32;
    int x = threadIdx.x & 31, y = threadIdx.x >> 5;   // 32 x 8
#pragma unroll
    for (int i = 0; i < 32; i += 8) {
        int r = r0 + y + i, c = c0 + x;
        t[y + i][x] = (r < R && c < C) ? S[(size_t)r * C + c] : 0.0f;
    }
    __syncthreads();
#pragma unroll
    for (int i = 0; i < 32; i += 8) {
        int r = c0 + y + i, c = r0 + x;
        if (r < C && c < R) D[(size_t)r * R + c] = f2tf_f(t[x][y + i]);
    }
}

// ---------------------------------------------------------------------------
// Projection weight prep: Bt(32 x 256), Bt[n][kk] = [W_re;W_im][kk][n]
// ---------------------------------------------------------------------------
__global__ __launch_bounds__(256) void proj_wprep(
    const float* __restrict__ Wre, const float* __restrict__ Wim,
    float* __restrict__ Bt)
{
    int i = blockIdx.x * 256 + threadIdx.x;
    if (i < 32 * 256) {
        int n = i >> 8, kk = i & 255;
        float v = (kk < 128) ? Wre[kk * 32 + n] : Wim[(kk - 128) * 32 + n];
        Bt[i] = f2tf_f(v);
    }
}

// ---------------------------------------------------------------------------
// TF32 tensor-core GEMM, cp.async 3-stage pipeline (unchanged from R5):
//   C(M,Nn) = A(M,Kd) * Bt(Nn,Kd)^T; A and Bt pre-rounded to tf32.
// ---------------------------------------------------------------------------
#define GKC 32
#define STAGE_BYTES 32768
#define GEMM_SMEM  (3 * STAGE_BYTES)

__global__ __launch_bounds__(256, 2) void gemm_cp(
    const float* __restrict__ A, const float* __restrict__ Bt,
    float* __restrict__ C, int M, int Nn, int Kd)
{
    extern __shared__ float smem[];
    const uint32_t sbase = smem_u32(smem);
    const int tid = threadIdx.x;
    const int wid = tid >> 5, lane = tid & 31;
    const int gid = lane >> 2, tig = lane & 3;
    const int wm = (wid >> 1) * 32;
    const int wn = (wid & 1) * 64;
    const int row0 = blockIdx.y * 128;
    const int col0 = blockIdx.x * 128;
    const int NCH = Kd / GKC;

    float acc[2][8][4];
#pragma unroll
    for (int mi = 0; mi < 2; ++mi)
#pragma unroll
        for (int ni = 0; ni < 8; ++ni)
#pragma unroll
            for (int q = 0; q < 4; ++q) acc[mi][ni][q] = 0.0f;

    int prow[4], pseg[4];
    uint32_t poff[4];
#pragma unroll
    for (int i = 0; i < 4; ++i) {
        int idx = i * 256 + tid;
        prow[i] = idx >> 3;
        pseg[i] = idx & 7;
        poff[i] = (uint32_t)(prow[i] * 128 + ((pseg[i] ^ (prow[i] & 7)) << 4));
    }

#define PREFETCH(pc) do {                                                     \
    if ((pc) < NCH) {                                                         \
        int k0 = (pc) * GKC;                                                  \
        uint32_t stb = sbase + ((pc) % 3) * STAGE_BYTES;                      \
        _Pragma("unroll")                                                     \
        for (int i = 0; i < 4; ++i) {                                         \
            cpa16(stb + poff[i],                                              \
                  A + (size_t)(row0 + prow[i]) * Kd + k0 + pseg[i] * 4, 16);  \
            int nr = col0 + prow[i];                                          \
            int ok = (nr < Nn);                                               \
            cpa16(stb + 16384 + poff[i],                                      \
                  Bt + (size_t)(ok ? nr : 0) * Kd + k0 + pseg[i] * 4,         \
                  ok ? 16 : 0);                                               \
        }                                                                     \
    }                                                                         \
    CP_COMMIT();                                                              \
} while (0)

    PREFETCH(0);
    PREFETCH(1);

    for (int c = 0; c < NCH; ++c) {
        CP_WAIT1();
        __syncthreads();
        PREFETCH(c + 2);

        const float* Af = smem + (c % 3) * 8192;
        const float* Bf = Af + 4096;

#pragma unroll
        for (int kk = 0; kk < 4; ++kk) {
            uint32_t af[2][4];
#pragma unroll
            for (int mi = 0; mi < 2; ++mi) {
                int ra = wm + mi * 16 + gid;
                int s0 = ((kk * 2) ^ (ra & 7)) << 2;
                int s1 = ((kk * 2 + 1) ^ (ra & 7)) << 2;
                int base = ra * 32 + tig;
                af[mi][0] = __float_as_uint(Af[base + s0]);
                af[mi][1] = __float_as_uint(Af[base + s0 + 256]);
                af[mi][2] = __float_as_uint(Af[base + s1]);
                af[mi][3] = __float_as_uint(Af[base + s1 + 256]);
            }
            uint32_t bf[8][2];
#pragma unroll
            for (int ni = 0; ni < 8; ++ni) {
                int rb = wn + ni * 8 + gid;
                int base = rb * 32 + tig;
                bf[ni][0] = __float_as_uint(Bf[base + (((kk * 2) ^ (rb & 7)) << 2)]);
                bf[ni][1] = __float_as_uint(Bf[base + (((kk * 2 + 1) ^ (rb & 7)) << 2)]);
            }
#pragma unroll
            for (int mi = 0; mi < 2; ++mi)
#pragma unroll
                for (int ni = 0; ni < 8; ++ni)
                    mma_tf32(acc[mi][ni], af[mi], bf[ni]);
        }
    }
#undef PREFETCH

#pragma unroll
    for (int mi = 0; mi < 2; ++mi) {
        int r0 = row0 + wm + mi * 16 + gid;
#pragma unroll
        for (int ni = 0; ni < 8; ++ni) {
            int cc = col0 + wn + ni * 8 + tig * 2;
            if (cc < Nn) {
                *(float2*)(C + (size_t)r0 * Nn + cc) =
                    make_float2(acc[mi][ni][0], acc[mi][ni][1]);
                *(float2*)(C + (size_t)(r0 + 8) * Nn + cc) =
                    make_float2(acc[mi][ni][2], acc[mi][ni][3]);
            }
        }
    }
}

// ---------------------------------------------------------------------------
// Causal depthwise conv1d, kernel 4, left pad 3 — float4 over channels.
// TOT = 2080 = 520 float4.
// ---------------------------------------------------------------------------
#define TOT4 (TOT / 4)
__global__ __launch_bounds__(256) void conv_kernel(
    const float4* __restrict__ z, const float4* __restrict__ wc,
    const float4* __restrict__ bc, float4* __restrict__ zc)
{
    int idx = blockIdx.x * 256 + threadIdx.x;
    const int total = BB * LL * TOT4;
    if (idx >= total) return;
    int c  = idx % TOT4;
    int bl = idx / TOT4;
    int l  = bl % LL;

    float4 acc = bc[c];
#pragma unroll
    for (int jk = 0; jk < CONVK; ++jk) {
        int ls = l - 3 + jk;
        if (ls >= 0) {
            float4 w = wc[jk * TOT4 + c];
            float4 v = z[(size_t)(bl - 3 + jk) * TOT4 + c];
            acc.x += w.x * v.x; acc.y += w.y * v.y;
            acc.z += w.z * v.z; acc.w += w.w * v.w;
        }
    }
    zc[idx] = acc;
}

// ---------------------------------------------------------------------------
// Shared per-thread scan preamble
// ---------------------------------------------------------------------------
struct ScanConst {
    float theta_t, w0, w1, w2, ss, rate;
    bool decay;
};

__device__ __forceinline__ ScanConst scan_consts(
    int k, int j, const float* theta, const float* dslopes,
    const float* aslopes, const float* sscale, const float* dlogits)
{
    ScanConst sc;
    sc.theta_t = theta[k * (HD * MT) + j];
    float dl0 = dlogits[0], dl1 = dlogits[1], dl2 = dlogits[2];
    float mx = fmaxf(dl0, fmaxf(dl1, dl2));
    float e0 = __expf(dl0 - mx), e1 = __expf(dl1 - mx), e2 = __expf(dl2 - mx);
    float dinv = 1.0f / (e0 + e1 + e2);
    sc.w0 = e0 * dinv; sc.w1 = e1 * dinv; sc.w2 = e2 * dinv;
    sc.ss = sscale[k];
    sc.decay = (k < KH - ANCHOR);
    float slope = sc.decay ? dslopes[k] : aslopes[k - (KH - ANCHOR)];
    sc.rate = logf(1.0f + expf(slope));
    return sc;
}

// tw is maintained by the caller via a geometric recurrence.
__device__ __forceinline__ void scan_step(
    const ScanConst& sc, float xv, float sv, float tw,
    float& accRe, float& accIm, float& accDen)
{
    float parg = fminf(fmaxf(sc.ss * sv, -20.0f), 20.0f);
    float p = __expf(parg);
    float pw = p * tw;
    float phi = xv * sc.theta_t;
    float sbv, cbv;
    __sincosf(phi, &sbv, &cbv);
    float poly = sc.w0 + sc.w1 * xv - sc.w2 * xv * xv;
    float ppw = pw * poly;
    accDen += pw;
    accRe  += ppw * cbv;
    accIm  += ppw * sbv;
}

__device__ __forceinline__ void tw_init(const ScanConst& sc, int lstart,
                                        float& tw, float& twm)
{
    if (sc.decay) {
        tw  = __expf(-sc.rate * (float)(LL - 1 - lstart));
        twm = __expf(sc.rate);
    } else {
        tw  = __expf(-sc.rate * (float)lstart);
        twm = __expf(-sc.rate);
    }
}

// ---------------------------------------------------------------------------
// Scan pass 1: per-chunk lane sums. grid = B*K*NC, block = 128.
// ---------------------------------------------------------------------------
__global__ __launch_bounds__(128) void scan_part1(
    const float* __restrict__ zc, const float* __restrict__ theta,
    const float* __restrict__ dslopes, const float* __restrict__ aslopes,
    const float* __restrict__ sscale, const float* __restrict__ dlogits,
    float* __restrict__ part)
{
    __shared__ float sxv[TT * 32];
    __shared__ float ssv[TT];

    const int chunk = blockIdx.x % NC;
    const int bk    = blockIdx.x / NC;
    const int k  = bk % KH;
    const int bb = bk / KH;
    const int tid = threadIdx.x;
    const int j = tid, h = j >> 2;

    const ScanConst sc = scan_consts(k, j, theta, dslopes, aslopes, sscale, dlogits);
    float tw, twm;
    tw_init(sc, chunk * CL, tw, twm);

    float accRe = 0.0f, accIm = 0.0f, accDen = 0.0f;
    const size_t baserow = (size_t)bb * LL;

    for (int l0 = chunk * CL; l0 < chunk * CL + CL; l0 += TT) {
        __syncthreads();
        {
            int v = tid;
            int t = v >> 5, hh = v & 31;
            sxv[v] = zc[(baserow + l0 + t) * (size_t)TOT + (size_t)k * HD + hh];
            v = tid + 128; t = v >> 5; hh = v & 31;
            sxv[v] = zc[(baserow + l0 + t) * (size_t)TOT + (size_t)k * HD + hh];
            if (tid < TT)
                ssv[tid] = zc[(baserow + l0 + tid) * (size_t)TOT + 2 * DM + k];
        }
        __syncthreads();
#pragma unroll
        for (int t = 0; t < TT; ++t) {
            scan_step(sc, sxv[t * 32 + h], ssv[t], tw, accRe, accIm, accDen);
            tw *= twm;
        }
    }

    float* p = part + (size_t)blockIdx.x * 384;
    p[j] = accRe; p[128 + j] = accIm; p[256 + j] = accDen;
}

// ---------------------------------------------------------------------------
// Scan pass 2: exclusive prefix over chunks, in place. grid = B*K, block 128.
// ---------------------------------------------------------------------------
__global__ __launch_bounds__(128) void scan_part2(float* __restrict__ part)
{
    const int bk = blockIdx.x;
    const int j = threadIdx.x;
    float rRe = 0.0f, rIm = 0.0f, rDen = 0.0f;
    for (int c = 0; c < NC; ++c) {
        float* p = part + ((size_t)bk * NC + c) * 384;
        float tRe = p[j], tIm = p[128 + j], tDen = p[256 + j];
        p[j] = rRe; p[128 + j] = rIm; p[256 + j] = rDen;
        rRe += tRe; rIm += tIm; rDen += tDen;
    }
}

// ---------------------------------------------------------------------------
// Scan pass 3 (fused): scan + joint RMS norm + in-SMEM projection GEMM
// (mma.sync) + SiLU gate. Writes g directly. grid = B*K*NC, block = 128.
//
// SMEM (floats, stride 260 to kill bank conflicts):
//   Ws   [32 x 260]  projection weights (32 rows x 256 cols used)
//   As   [16 x 260]  normalized [re|im] tile for a 16-step group
//   ssq  [TT * 128], sxv [TT*32], sgv [16*32], ssv [TT], srsq [TT]
// ---------------------------------------------------------------------------
#define P3_WS   0
#define P3_AS   (32 * 260)                 // 8320
#define P3_SSQ  (P3_AS + 16 * 260)         // 12480
#define P3_SXV  (P3_SSQ + TT * 128)        // 13504
#define P3_SGV  (P3_SXV + TT * 32)         // 13760
#define P3_SSV  (P3_SGV + 16 * 32)         // 14272
#define P3_SRSQ (P3_SSV + TT)              // 14280
#define P3_SMEM ((P3_SRSQ + TT) * 4)       // 57152 bytes

__global__ __launch_bounds__(128) void scan_part3(
    const float* __restrict__ zc, const float* __restrict__ theta,
    const float* __restrict__ dslopes, const float* __restrict__ aslopes,
    const float* __restrict__ sscale, const float* __restrict__ dlogits,
    const float* __restrict__ nscale, const float* __restrict__ Wp,
    const float* __restrict__ part, float* __restrict__ g_out)
{
    extern __shared__ float sm[];
    float* Ws   = sm + P3_WS;
    float* As   = sm + P3_AS;
    float* ssq  = sm + P3_SSQ;
    float* sxv  = sm + P3_SXV;
    float* sgv  = sm + P3_SGV;
    float* ssv  = sm + P3_SSV;
    float* srsq = sm + P3_SRSQ;

    const int chunk = blockIdx.x % NC;
    const int bk    = blockIdx.x / NC;
    const int k  = bk % KH;
    const int bb = bk / KH;
    const int tid = threadIdx.x;
    const int j = tid, h = j >> 2;
    const int lane = tid & 31;
    const int warp = tid >> 5;
    const int gid = lane >> 2, tig = lane & 3;

    const ScanConst sc = scan_consts(k, j, theta, dslopes, aslopes, sscale, dlogits);
    const float ns_re = nscale[j];
    const float ns_im = nscale[HD * MT + j];
    float tw, twm;
    tw_init(sc, chunk * CL, tw, twm);

    // load projection weights (32 x 256) into padded smem
    for (int i = tid; i < 32 * 256; i += 128) {
        int row = i >> 8, col = i & 255;
        Ws[row * 260 + col] = Wp[i];
    }

    const float* pfx = part + (size_t)blockIdx.x * 384;
    float accRe = pfx[j], accIm = pfx[128 + j], accDen = pfx[256 + j];
    const size_t baserow = (size_t)bb * LL;

    for (int grp = 0; grp < CL / 16; ++grp) {
        const int gl0 = chunk * CL + grp * 16;

#pragma unroll
        for (int sub = 0; sub < 2; ++sub) {
            const int l0 = gl0 + sub * TT;
            __syncthreads();
            {
                int v = tid;
                int t = v >> 5, hh = v & 31;
                size_t rowA = (baserow + l0 + t) * (size_t)TOT;
                sxv[v] = zc[rowA + (size_t)k * HD + hh];
                sgv[(sub * TT + t) * 32 + hh] = zc[rowA + DM + (size_t)k * HD + hh];
                v = tid + 128; t = v >> 5; hh = v & 31;
                size_t rowB = (baserow + l0 + t) * (size_t)TOT;
                sxv[v] = zc[rowB + (size_t)k * HD + hh];
                sgv[(sub * TT + t) * 32 + hh] = zc[rowB + DM + (size_t)k * HD + hh];
                if (tid < TT)
                    ssv[tid] = zc[(baserow + l0 + tid) * (size_t)TOT + 2 * DM + k];
            }
            __syncthreads();

            float re[TT], im[TT];
#pragma unroll
            for (int t = 0; t < TT; ++t) {
                scan_step(sc, sxv[t * 32 + h], ssv[t], tw, accRe, accIm, accDen);
                tw *= twm;
                float invd = 1.0f / fmaxf(accDen, 1e-4f);
                re[t] = accRe * invd;
                im[t] = accIm * invd;
                ssq[t * 128 + j] = re[t] * re[t] + im[t] * im[t];
            }
            __syncthreads();

            {
                int tt = warp * 2;
#pragma unroll
                for (int q = 0; q < 2; ++q, ++tt) {
                    float v = ssq[tt * 128 + lane] + ssq[tt * 128 + lane + 32]
                            + ssq[tt * 128 + lane + 64] + ssq[tt * 128 + lane + 96];
#pragma unroll
                    for (int off = 16; off; off >>= 1)
                        v += __shfl_xor_sync(0xffffffffu, v, off);
                    if (lane == 0)
                        srsq[tt] = rsqrtf(v * (1.0f / (2.0f * HD * MT)) + 1e-5f);
                }
            }
            __syncthreads();

#pragma unroll
            for (int t = 0; t < TT; ++t) {
                float r = srsq[t];
                int row = sub * TT + t;
                As[row * 260 + j]       = f2tf_f(re[t] * r * ns_re);
                As[row * 260 + 128 + j] = f2tf_f(im[t] * r * ns_im);
            }
        }
        __syncthreads();   // As tile (16 x 256) complete

        // projection: C(16 x 32) = As(16 x 256) @ Ws(32 x 256)^T
        // warp w handles cols w*8 .. w*8+7; 32 k-steps of 8.
        float acc[4] = {0.0f, 0.0f, 0.0f, 0.0f};
#pragma unroll
        for (int ks = 0; ks < 32; ++ks) {
            int kb = ks * 8;
            uint32_t af[4], bf[2];
            int abase = gid * 260 + kb + tig;
            af[0] = __float_as_uint(As[abase]);
            af[1] = __float_as_uint(As[abase + 8 * 260]);
            af[2] = __float_as_uint(As[abase + 4]);
            af[3] = __float_as_uint(As[abase + 8 * 260 + 4]);
            int bbase = (warp * 8 + gid) * 260 + kb + tig;
            bf[0] = __float_as_uint(Ws[bbase]);
            bf[1] = __float_as_uint(Ws[bbase + 4]);
            mma_tf32(acc, af, bf);
        }

        // epilogue: gate + tf32 round + store to g
#pragma unroll
        for (int rg = 0; rg < 2; ++rg) {
            int m = gid + rg * 8;           // step within group
            int l = gl0 + m;
            int hh = warp * 8 + tig * 2;
            float gz0 = sgv[m * 32 + hh];
            float gz1 = sgv[m * 32 + hh + 1];
            float s0 = gz0 / (1.0f + __expf(-gz0));
            float s1 = gz1 / (1.0f + __expf(-gz1));
            *(float2*)(g_out + (baserow + l) * (size_t)DM + (size_t)k * HD + hh) =
                make_float2(f2tf_f(acc[rg * 2 + 0] * s0),
                            f2tf_f(acc[rg * 2 + 1] * s1));
        }
    }
}

// ---------------------------------------------------------------------------
extern "C" void kernel_launch(void* const* d_in, const int* in_sizes, int n_in,
                              void* d_out, int out_size)
{
    const float* x       = (const float*)d_in[0];
    const float* W_in    = (const float*)d_in[1];
    const float* w_conv  = (const float*)d_in[2];
    const float* b_conv  = (const float*)d_in[3];
    const float* theta   = (const float*)d_in[4];
    const float* dslopes = (const float*)d_in[5];
    const float* aslopes = (const float*)d_in[6];
    const float* sscale  = (const float*)d_in[7];
    const float* dlogits = (const float*)d_in[8];
    const float* nscale  = (const float*)d_in[9];
    const float* W_re    = (const float*)d_in[10];
    const float* W_im    = (const float*)d_in[11];
    const float* W_out   = (const float*)d_in[12];
    float* out = (float*)d_out;

    float *pz, *pzc, *pg, *px32, *pbt1, *pbt2, *pbtp, *ppart;
    cudaGetSymbolAddress((void**)&pz,    g_z);
    cudaGetSymbolAddress((void**)&pzc,   g_zc);
    cudaGetSymbolAddress((void**)&pg,    g_g);
    cudaGetSymbolAddress((void**)&px32,  g_x32);
    cudaGetSymbolAddress((void**)&pbt1,  g_bt1);
    cudaGetSymbolAddress((void**)&pbt2,  g_bt2);
    cudaGetSymbolAddress((void**)&pbtp,  g_btp);
    cudaGetSymbolAddress((void**)&ppart, g_part);

    static bool attr_set = false;
    if (!attr_set) {
        cudaFuncSetAttribute(gemm_cp,
                             cudaFuncAttributeMaxDynamicSharedMemorySize, GEMM_SMEM);
        cudaFuncSetAttribute(scan_part3,
                             cudaFuncAttributeMaxDynamicSharedMemorySize, P3_SMEM);
        attr_set = true;
    }

    // 0) weight prep + x rounding
    transpose_k<<<dim3((TOT + 31) / 32, DM / 32), 256>>>(W_in, pbt1, DM, TOT);
    transpose_k<<<dim3(DM / 32, DM / 32), 256>>>(W_out, pbt2, DM, DM);
    proj_wprep<<<32, 256>>>(W_re, W_im, pbtp);
    {
        int n4 = BB * LL * DM / 4;
        round_tf32_k<<<(n4 + 255) / 256, 256>>>((const float4*)x, (float4*)px32, n4);
    }

    // 1) z = x @ W_in   — TF32 mma.sync, cp.async pipeline
    {
        dim3 grid((TOT + 127) / 128, (BB * LL) / 128);
        gemm_cp<<<grid, 256, GEMM_SMEM>>>(px32, pbt1, pz, BB * LL, TOT, DM);
    }
    // 2) causal depthwise conv (float4)
    {
        int total = BB * LL * TOT4;
        conv_kernel<<<(total + 255) / 256, 256>>>(
            (const float4*)pz, (const float4*)w_conv,
            (const float4*)b_conv, (float4*)pzc);
    }
    // 3) chunked parallel scan; part3 fuses RMS norm + projection + gate
    scan_part1<<<BB * KH * NC, 128>>>(pzc, theta, dslopes, aslopes,
                                      sscale, dlogits, ppart);
    scan_part2<<<BB * KH, 128>>>(ppart);
    scan_part3<<<BB * KH * NC, 128, P3_SMEM>>>(pzc, theta, dslopes, aslopes,
                                               sscale, dlogits, nscale,
                                               pbtp, ppart, pg);
    // 4) out = g @ W_out — TF32 mma.sync, cp.async pipeline
    {
        dim3 grid(DM / 128, (BB * LL) / 128);
        gemm_cp<<<grid, 256, GEMM_SMEM>>>(pg, pbt2, out, BB * LL, DM, DM);
    }
}